// round 9
// baseline (speedup 1.0000x reference)
#include <cuda_runtime.h>

// ---------------------------------------------------------------------------
// AttentiveStateMLP — persistent block-tiled, 512-thread version.
// R7 ncu: fma 20%, issue 30.7%, occ 12.5% -> latency/barrier bound at 8 warps,
// with phase-4/5 weight loads going to global (L1D ~0 due to smem carveout).
// R8: 16 warps/SM, all hot weights in smem (Wo resident, Wp staged into dead
// sY region per tile), every phase spread across all 512 threads, padded sY
// strides (260/1304) for conflict-free attention accesses.
// ---------------------------------------------------------------------------

#define BATCH   131072
#define RTILE   8
#define NTILES  (BATCH / RTILE)     // 16384
#define NTHR    512

#define TS 260                       // token stride in sY (floats)
#define YS 1304                      // row stride in sY = 5*TS + 4

// smem layout (floats)
#define OFF_M    0                   // 36864 : combined M, k-major [c(144)][j(256)]
#define OFF_ENC  36864               // 2560  : encoder weights, k-major
#define OFF_WO   39424               // 4096  : WoT k-major [c(64)][j(64)]
#define OFF_MB   43520               // 1280  : per-token M bias
#define OFF_B    44800               // 464   : encbias144|bo64|gamma64|beta64|bp128
#define OFF_X    45264               // 512   : x tile 8 x 64
#define OFF_F    45776               // 1152  : features 8 x 144
#define OFF_Y    46928               // 10432 : 8 x YS  (tok|q/ctx|k/h|v) ; Wp staging
#define OFF_P    57360               // 512   : pooled 8 x 64
#define SMEM_FL  57872
#define SMEM_BYTES (SMEM_FL * 4)     // 231488 bytes (max dyn smem 232448)

// enc sub-offsets within OFF_ENC
#define E_PHYS 0       // 29 x 64
#define E_OBJ  1856    // 15 x 32
#define E_MINE 2336    // 8 x 16
#define E_PROG 2464    // 3 x 16
#define E_SEQ  2512    // 3 x 16

__device__ float g_M[144 * 256];   // k-major combined matrix [P_s ; Wqkv@P_s]
__device__ float g_Mb[5 * 256];    // per-token bias for M outputs
__device__ float g_encT[2560];     // k-major encoder weights
__device__ float g_WoT[64 * 64];   // WoT[c*64+j] = Wo[j][c]
__device__ float g_WpT[64 * 128];  // WpT[c*128+o] = Wp[o][c]

// ---------------------------------------------------------------------------
__global__ void prep_kernel(
    const float* __restrict__ Wqkv, const float* __restrict__ bqkv,
    const float* __restrict__ P_phys, const float* __restrict__ pb_phys,
    const float* __restrict__ P_obj,  const float* __restrict__ pb_obj,
    const float* __restrict__ P_mine, const float* __restrict__ pb_mine,
    const float* __restrict__ P_prog, const float* __restrict__ pb_prog,
    const float* __restrict__ P_seq,  const float* __restrict__ pb_seq,
    const float* __restrict__ W_phys, const float* __restrict__ W_obj,
    const float* __restrict__ W_mine, const float* __restrict__ W_prog,
    const float* __restrict__ W_seq,
    const float* __restrict__ Wo, const float* __restrict__ Wp)
{
    int idx = blockIdx.x * blockDim.x + threadIdx.x;

    if (idx < 36864) {                       // g_M[cg*256 + j]
        int cg = idx >> 8;
        int j  = idx & 255;
        const float* P; int dim, c;
        if (cg < 64)       { P = P_phys; dim = 64; c = cg; }
        else if (cg < 96)  { P = P_obj;  dim = 32; c = cg - 64; }
        else if (cg < 112) { P = P_mine; dim = 16; c = cg - 96; }
        else if (cg < 128) { P = P_prog; dim = 16; c = cg - 112; }
        else               { P = P_seq;  dim = 16; c = cg - 128; }
        float v;
        if (j < 64) {
            v = P[j * dim + c];
        } else {
            int jq = j - 64;
            float a = 0.f;
            for (int k = 0; k < 64; k++)
                a = fmaf(Wqkv[jq * 64 + k], P[k * dim + c], a);
            v = a;
        }
        g_M[idx] = v;
        return;
    }
    int i2 = idx - 36864;                    // g_Mb: 1280
    if (i2 < 1280) {
        int s = i2 >> 8;
        int j = i2 & 255;
        const float* pb = (s == 0) ? pb_phys : (s == 1) ? pb_obj :
                          (s == 2) ? pb_mine : (s == 3) ? pb_prog : pb_seq;
        float v;
        if (j < 64) {
            v = pb[j];
        } else {
            int jq = j - 64;
            float a = bqkv[jq];
            for (int k = 0; k < 64; k++)
                a = fmaf(Wqkv[jq * 64 + k], pb[k], a);
            v = a;
        }
        g_Mb[i2] = v;
        return;
    }
    int i3 = idx - 38144;                    // g_encT: 2560
    if (i3 < 2560) {
        float v;
        if (i3 < E_OBJ)        { int t = i3;          v = W_phys[(t & 63) * 29 + (t >> 6)]; }
        else if (i3 < E_MINE)  { int t = i3 - E_OBJ;  v = W_obj [(t & 31) * 15 + (t >> 5)]; }
        else if (i3 < E_PROG)  { int t = i3 - E_MINE; v = W_mine[(t & 15) *  8 + (t >> 4)]; }
        else if (i3 < E_SEQ)   { int t = i3 - E_PROG; v = W_prog[(t & 15) *  3 + (t >> 4)]; }
        else                   { int t = i3 - E_SEQ;  v = W_seq [(t & 15) *  3 + (t >> 4)]; }
        g_encT[i3] = v;
        return;
    }
    int i4 = idx - 40704;                    // g_WoT: 4096
    if (i4 < 4096) {
        int c = i4 >> 6, j = i4 & 63;
        g_WoT[i4] = Wo[j * 64 + c];
        return;
    }
    int i5 = idx - 44800;                    // g_WpT: 8192
    if (i5 < 8192) {
        int c = i5 >> 7, o = i5 & 127;
        g_WpT[i5] = Wp[o * 64 + c];
    }
}

// ---------------------------------------------------------------------------
template <int SOFF, int SDIM>
__device__ __forceinline__ void mgemm_seg4(const float* __restrict__ sM,
                                           const float* __restrict__ F0,
                                           float* acc, int j)
{
    const float* Ms = sM + SOFF * 256 + j;
    #pragma unroll
    for (int c = 0; c < SDIM; c += 4) {
        float w0 = Ms[(c + 0) * 256];
        float w1 = Ms[(c + 1) * 256];
        float w2 = Ms[(c + 2) * 256];
        float w3 = Ms[(c + 3) * 256];
        #pragma unroll
        for (int r = 0; r < 4; r++) {
            float4 f = *reinterpret_cast<const float4*>(F0 + r * 144 + SOFF + c);
            acc[r] = fmaf(f.x, w0, fmaf(f.y, w1, fmaf(f.z, w2, fmaf(f.w, w3, acc[r]))));
        }
    }
}

__global__ __launch_bounds__(NTHR, 1)
void fused_kernel(const float* __restrict__ x,
                  const float* __restrict__ b_phys, const float* __restrict__ b_obj,
                  const float* __restrict__ b_mine, const float* __restrict__ b_prog,
                  const float* __restrict__ b_seq,
                  const float* __restrict__ bo, const float* __restrict__ gamma,
                  const float* __restrict__ beta, const float* __restrict__ bp,
                  float* __restrict__ out)
{
    extern __shared__ float sm[];
    float* sM   = sm + OFF_M;
    float* sEnc = sm + OFF_ENC;
    float* sWo  = sm + OFF_WO;
    float* sMb  = sm + OFF_MB;
    float* sB   = sm + OFF_B;
    float* sX   = sm + OFF_X;
    float* sF   = sm + OFF_F;
    float* sY   = sm + OFF_Y;
    float* sP   = sm + OFF_P;

    const int tid = threadIdx.x;

    // ---- preload all weights into smem once per block ----
    for (int i = tid; i < 36864; i += NTHR) sM[i]   = g_M[i];
    for (int i = tid; i < 2560;  i += NTHR) sEnc[i] = g_encT[i];
    for (int i = tid; i < 4096;  i += NTHR) sWo[i]  = g_WoT[i];
    for (int i = tid; i < 1280;  i += NTHR) sMb[i]  = g_Mb[i];
    for (int i = tid; i < 464; i += NTHR) {
        float v;
        if (i < 64)       v = b_phys[i];
        else if (i < 96)  v = b_obj[i - 64];
        else if (i < 112) v = b_mine[i - 96];
        else if (i < 128) v = b_prog[i - 112];
        else if (i < 144) v = b_seq[i - 128];
        else if (i < 208) v = bo[i - 144];
        else if (i < 272) v = gamma[i - 208];
        else if (i < 336) v = beta[i - 272];
        else              v = bp[i - 336];
        sB[i] = v;
    }
    __syncthreads();

    for (int tile = blockIdx.x; tile < NTILES; tile += gridDim.x) {
        const int base = tile * RTILE;

        // ---- P0: load x tile (coalesced) ----
        if (tid < RTILE * 58) {
            int r = tid / 58, c = tid - r * 58;
            sX[r * 64 + c] = x[(size_t)base * 58 + tid];
        }
        __syncthreads();

        // ---- P1: encoders, thread-per-output ----
        {
            int r = tid >> 6, j = tid & 63;          // phys: 8 x 64 = 512
            const float* xr = sX + r * 64;
            float a = sB[j];
            #pragma unroll
            for (int c = 0; c < 29; c++)
                a = fmaf(sEnc[E_PHYS + c * 64 + j], xr[c], a);
            sF[r * 144 + j] = fmaxf(a, 0.f);
        }
        if (tid < 256) {                              // obj: 8 x 32
            int r = tid >> 5, j = tid & 31;
            const float* xr = sX + r * 64;
            float a = sB[64 + j];
            #pragma unroll
            for (int c = 0; c < 15; c++)
                a = fmaf(sEnc[E_OBJ + c * 32 + j], xr[29 + c], a);
            sF[r * 144 + 64 + j] = fmaxf(a, 0.f);
        }
        if (tid < 384) {                              // mine/prog/seq: 3 x 8 x 16
            int seg = tid >> 7;
            int t = tid & 127;
            int r = t >> 4, j = t & 15;
            const float* xr = sX + r * 64;
            const float* W; int xo, kk, oo;
            float a;
            if (seg == 0)      { W = sEnc + E_MINE; xo = 44; kk = 8; oo = 96;  a = sB[96 + j]; }
            else if (seg == 1) { W = sEnc + E_PROG; xo = 52; kk = 3; oo = 112; a = sB[112 + j]; }
            else               { W = sEnc + E_SEQ;  xo = 55; kk = 3; oo = 128; a = sB[128 + j]; }
            for (int c = 0; c < kk; c++)
                a = fmaf(W[c * 16 + j], xr[xo + c], a);
            sF[r * 144 + oo + j] = fmaxf(a, 0.f);
        }
        __syncthreads();

        // ---- P2: M-GEMM  Y[r][s][0:256] = tok|q|k|v ----
        {
            const int j  = tid & 255;
            const int g  = tid >> 8;        // 0,1 -> rows 4g..4g+3
            const float* F0 = sF + (g * 4) * 144;
            float* Y0 = sY + (g * 4) * YS;
            float acc[4];
            #pragma unroll
            for (int s = 0; s < 5; s++) {
                const float bias = sMb[s * 256 + j];
                #pragma unroll
                for (int r = 0; r < 4; r++) acc[r] = bias;
                switch (s) {
                    case 0:  mgemm_seg4<0,   64>(sM, F0, acc, j); break;
                    case 1:  mgemm_seg4<64,  32>(sM, F0, acc, j); break;
                    case 2:  mgemm_seg4<96,  16>(sM, F0, acc, j); break;
                    case 3:  mgemm_seg4<112, 16>(sM, F0, acc, j); break;
                    default: mgemm_seg4<128, 16>(sM, F0, acc, j); break;
                }
                // scatter j (0..255) into padded token slots: slot = j>>6, off = j&63
                const int slot = j >> 6, joff = j & 63;
                #pragma unroll
                for (int r = 0; r < 4; r++)
                    Y0[r * YS + s * TS + slot * 64 + joff] = acc[r];
            }
        }
        __syncthreads();

        // ---- P3: attention (160 units: row x head x query) ----
        if (tid < 160) {
            const int r  = tid & 7;
            const int hi = tid >> 3;
            const int h  = hi / 5;
            const int i  = hi - h * 5;
            float* Yr = sY + r * YS;
            const float4* q4 = reinterpret_cast<const float4*>(Yr + i * TS + 64 + h * 16);
            const float4 q0 = q4[0], q1 = q4[1], q2 = q4[2], q3 = q4[3];
            float sc[5];
            #pragma unroll
            for (int jt = 0; jt < 5; jt++) {
                const float4* k4 = reinterpret_cast<const float4*>(Yr + jt * TS + 128 + h * 16);
                float4 k0 = k4[0], k1 = k4[1], k2 = k4[2], k3 = k4[3];
                float d = q0.x * k0.x + q0.y * k0.y + q0.z * k0.z + q0.w * k0.w;
                d = fmaf(q1.x, k1.x, fmaf(q1.y, k1.y, fmaf(q1.z, k1.z, fmaf(q1.w, k1.w, d))));
                d = fmaf(q2.x, k2.x, fmaf(q2.y, k2.y, fmaf(q2.z, k2.z, fmaf(q2.w, k2.w, d))));
                d = fmaf(q3.x, k3.x, fmaf(q3.y, k3.y, fmaf(q3.z, k3.z, fmaf(q3.w, k3.w, d))));
                sc[jt] = d * 0.25f;
            }
            float mx = sc[0];
            #pragma unroll
            for (int jt = 1; jt < 5; jt++) mx = fmaxf(mx, sc[jt]);
            float sum = 0.f;
            #pragma unroll
            for (int jt = 0; jt < 5; jt++) { sc[jt] = __expf(sc[jt] - mx); sum += sc[jt]; }
            const float inv = 1.f / sum;
            #pragma unroll
            for (int tq = 0; tq < 4; tq++) {
                float4 c = make_float4(0.f, 0.f, 0.f, 0.f);
                #pragma unroll
                for (int jt = 0; jt < 5; jt++) {
                    const float4 v = reinterpret_cast<const float4*>(
                        Yr + jt * TS + 192 + h * 16)[tq];
                    c.x = fmaf(sc[jt], v.x, c.x);
                    c.y = fmaf(sc[jt], v.y, c.y);
                    c.z = fmaf(sc[jt], v.z, c.z);
                    c.w = fmaf(sc[jt], v.w, c.w);
                }
                c.x *= inv; c.y *= inv; c.z *= inv; c.w *= inv;
                reinterpret_cast<float4*>(Yr + i * TS + 64 + h * 16)[tq] = c;  // ctx->q slot
            }
        }
        __syncthreads();

        // ---- P4a: Wo projection + residual -> h (into k slot) ----
        {
            const int j = tid & 63;
            const int u = tid >> 6;          // row
            float* Yr = sY + u * YS;
            const float bov = sB[144 + j];
            float acc[5];
            #pragma unroll
            for (int s = 0; s < 5; s++) acc[s] = bov;
            #pragma unroll 4
            for (int c = 0; c < 64; c += 4) {
                float w0 = sWo[(c + 0) * 64 + j];
                float w1 = sWo[(c + 1) * 64 + j];
                float w2 = sWo[(c + 2) * 64 + j];
                float w3 = sWo[(c + 3) * 64 + j];
                #pragma unroll
                for (int s = 0; s < 5; s++) {
                    const float4 cv = *reinterpret_cast<const float4*>(Yr + s * TS + 64 + c);
                    acc[s] = fmaf(cv.x, w0, fmaf(cv.y, w1, fmaf(cv.z, w2, fmaf(cv.w, w3, acc[s]))));
                }
            }
            #pragma unroll
            for (int s = 0; s < 5; s++)
                Yr[s * TS + 128 + j] = Yr[s * TS + j] + acc[s];   // h = tok + proj
        }
        __syncthreads();

        // ---- P4b: LayerNorm + pool (warp per row) ----
        if (tid < 256) {
            const int r = tid >> 5, lane = tid & 31;
            const int j0 = lane * 2;
            float* Yr = sY + r * YS;
            const float g0 = sB[208 + j0], g1 = sB[208 + j0 + 1];
            const float be0 = sB[272 + j0], be1 = sB[272 + j0 + 1];
            float p0 = 0.f, p1 = 0.f;
            #pragma unroll
            for (int s = 0; s < 5; s++) {
                const float2 h2 = *reinterpret_cast<const float2*>(Yr + s * TS + 128 + j0);
                float sum = h2.x + h2.y;
                #pragma unroll
                for (int o = 16; o > 0; o >>= 1)
                    sum += __shfl_xor_sync(0xffffffff, sum, o);
                const float mu = sum * (1.f / 64.f);
                const float d0 = h2.x - mu, d1 = h2.y - mu;
                float v = d0 * d0 + d1 * d1;
                #pragma unroll
                for (int o = 16; o > 0; o >>= 1)
                    v += __shfl_xor_sync(0xffffffff, v, o);
                const float invstd = rsqrtf(v * (1.f / 64.f) + 1e-5f);
                p0 = fmaf(d0 * invstd, g0, p0 + be0);
                p1 = fmaf(d1 * invstd, g1, p1 + be1);
            }
            sP[r * 64 + j0]     = p0 * 0.2f;
            sP[r * 64 + j0 + 1] = p1 * 0.2f;
        }
        __syncthreads();

        // ---- P5: stage Wp into (dead) sY, then head GEMM ----
        {
            float4* dst = reinterpret_cast<float4*>(sY);
            const float4* src = reinterpret_cast<const float4*>(g_WpT);
            #pragma unroll
            for (int q = 0; q < 4; q++) dst[tid + q * NTHR] = src[tid + q * NTHR];
        }
        __syncthreads();
        {
            const int o  = tid & 127;
            const int r0 = (tid >> 7) * 2;           // rows r0, r0+1
            const float* sWp = sY;
            float a0 = sB[336 + o], a1 = a0;
            #pragma unroll 4
            for (int c = 0; c < 64; c += 4) {
                float w0 = sWp[(c + 0) * 128 + o];
                float w1 = sWp[(c + 1) * 128 + o];
                float w2 = sWp[(c + 2) * 128 + o];
                float w3 = sWp[(c + 3) * 128 + o];
                const float4 f0 = *reinterpret_cast<const float4*>(sP + r0 * 64 + c);
                const float4 f1 = *reinterpret_cast<const float4*>(sP + (r0 + 1) * 64 + c);
                a0 = fmaf(f0.x, w0, fmaf(f0.y, w1, fmaf(f0.z, w2, fmaf(f0.w, w3, a0))));
                a1 = fmaf(f1.x, w0, fmaf(f1.y, w1, fmaf(f1.z, w2, fmaf(f1.w, w3, a1))));
            }
            out[(size_t)(base + r0) * 128 + o]     = fmaxf(a0, 0.f);
            out[(size_t)(base + r0 + 1) * 128 + o] = fmaxf(a1, 0.f);
        }
        __syncthreads();
    }
}

// ---------------------------------------------------------------------------
extern "C" void kernel_launch(void* const* d_in, const int* in_sizes, int n_in,
                              void* d_out, int out_size)
{
    const float* x       = (const float*)d_in[0];
    const float* W_phys  = (const float*)d_in[1];
    const float* b_phys  = (const float*)d_in[2];
    const float* W_obj   = (const float*)d_in[3];
    const float* b_obj   = (const float*)d_in[4];
    const float* W_mine  = (const float*)d_in[5];
    const float* b_mine  = (const float*)d_in[6];
    const float* W_prog  = (const float*)d_in[7];
    const float* b_prog  = (const float*)d_in[8];
    const float* W_seq   = (const float*)d_in[9];
    const float* b_seq   = (const float*)d_in[10];
    const float* P_phys  = (const float*)d_in[11];
    const float* pb_phys = (const float*)d_in[12];
    const float* P_obj   = (const float*)d_in[13];
    const float* pb_obj  = (const float*)d_in[14];
    const float* P_mine  = (const float*)d_in[15];
    const float* pb_mine = (const float*)d_in[16];
    const float* P_prog  = (const float*)d_in[17];
    const float* pb_prog = (const float*)d_in[18];
    const float* P_seq   = (const float*)d_in[19];
    const float* pb_seq  = (const float*)d_in[20];
    const float* Wqkv    = (const float*)d_in[21];
    const float* bqkv    = (const float*)d_in[22];
    const float* Wo      = (const float*)d_in[23];
    const float* bo      = (const float*)d_in[24];
    const float* gamma   = (const float*)d_in[25];
    const float* beta    = (const float*)d_in[26];
    const float* Wp      = (const float*)d_in[27];
    const float* bp      = (const float*)d_in[28];
    float* out = (float*)d_out;

    cudaFuncSetAttribute(fused_kernel,
                         cudaFuncAttributeMaxDynamicSharedMemorySize,
                         SMEM_BYTES);

    int dev = 0, sms = 148;
    cudaGetDevice(&dev);
    cudaDeviceGetAttribute(&sms, cudaDevAttrMultiProcessorCount, dev);

    prep_kernel<<<207, 256>>>(Wqkv, bqkv,
                              P_phys, pb_phys, P_obj, pb_obj, P_mine, pb_mine,
                              P_prog, pb_prog, P_seq, pb_seq,
                              W_phys, W_obj, W_mine, W_prog, W_seq,
                              Wo, Wp);

    fused_kernel<<<sms, NTHR, SMEM_BYTES>>>(
        x, b_phys, b_obj, b_mine, b_prog, b_seq,
        bo, gamma, beta, bp, out);
}

// round 10
// speedup vs baseline: 1.0029x; 1.0029x over previous
#include <cuda_runtime.h>

// ---------------------------------------------------------------------------
// AttentiveStateMLP — persistent block-tiled, 512-thread version.
// R7 ncu: fma 20%, issue 30.7%, occ 12.5% -> latency/barrier bound at 8 warps,
// with phase-4/5 weight loads going to global (L1D ~0 due to smem carveout).
// R8: 16 warps/SM, all hot weights in smem (Wo resident, Wp staged into dead
// sY region per tile), every phase spread across all 512 threads, padded sY
// strides (260/1304) for conflict-free attention accesses.
// ---------------------------------------------------------------------------

#define BATCH   131072
#define RTILE   8
#define NTILES  (BATCH / RTILE)     // 16384
#define NTHR    512

#define TS 260                       // token stride in sY (floats)
#define YS 1304                      // row stride in sY = 5*TS + 4

// smem layout (floats)
#define OFF_M    0                   // 36864 : combined M, k-major [c(144)][j(256)]
#define OFF_ENC  36864               // 2560  : encoder weights, k-major
#define OFF_WO   39424               // 4096  : WoT k-major [c(64)][j(64)]
#define OFF_MB   43520               // 1280  : per-token M bias
#define OFF_B    44800               // 464   : encbias144|bo64|gamma64|beta64|bp128
#define OFF_X    45264               // 512   : x tile 8 x 64
#define OFF_F    45776               // 1152  : features 8 x 144
#define OFF_Y    46928               // 10432 : 8 x YS  (tok|q/ctx|k/h|v) ; Wp staging
#define OFF_P    57360               // 512   : pooled 8 x 64
#define SMEM_FL  57872
#define SMEM_BYTES (SMEM_FL * 4)     // 231488 bytes (max dyn smem 232448)

// enc sub-offsets within OFF_ENC
#define E_PHYS 0       // 29 x 64
#define E_OBJ  1856    // 15 x 32
#define E_MINE 2336    // 8 x 16
#define E_PROG 2464    // 3 x 16
#define E_SEQ  2512    // 3 x 16

__device__ float g_M[144 * 256];   // k-major combined matrix [P_s ; Wqkv@P_s]
__device__ float g_Mb[5 * 256];    // per-token bias for M outputs
__device__ float g_encT[2560];     // k-major encoder weights
__device__ float g_WoT[64 * 64];   // WoT[c*64+j] = Wo[j][c]
__device__ float g_WpT[64 * 128];  // WpT[c*128+o] = Wp[o][c]

// ---------------------------------------------------------------------------
__global__ void prep_kernel(
    const float* __restrict__ Wqkv, const float* __restrict__ bqkv,
    const float* __restrict__ P_phys, const float* __restrict__ pb_phys,
    const float* __restrict__ P_obj,  const float* __restrict__ pb_obj,
    const float* __restrict__ P_mine, const float* __restrict__ pb_mine,
    const float* __restrict__ P_prog, const float* __restrict__ pb_prog,
    const float* __restrict__ P_seq,  const float* __restrict__ pb_seq,
    const float* __restrict__ W_phys, const float* __restrict__ W_obj,
    const float* __restrict__ W_mine, const float* __restrict__ W_prog,
    const float* __restrict__ W_seq,
    const float* __restrict__ Wo, const float* __restrict__ Wp)
{
    int idx = blockIdx.x * blockDim.x + threadIdx.x;

    if (idx < 36864) {                       // g_M[cg*256 + j]
        int cg = idx >> 8;
        int j  = idx & 255;
        const float* P; int dim, c;
        if (cg < 64)       { P = P_phys; dim = 64; c = cg; }
        else if (cg < 96)  { P = P_obj;  dim = 32; c = cg - 64; }
        else if (cg < 112) { P = P_mine; dim = 16; c = cg - 96; }
        else if (cg < 128) { P = P_prog; dim = 16; c = cg - 112; }
        else               { P = P_seq;  dim = 16; c = cg - 128; }
        float v;
        if (j < 64) {
            v = P[j * dim + c];
        } else {
            int jq = j - 64;
            float a = 0.f;
            for (int k = 0; k < 64; k++)
                a = fmaf(Wqkv[jq * 64 + k], P[k * dim + c], a);
            v = a;
        }
        g_M[idx] = v;
        return;
    }
    int i2 = idx - 36864;                    // g_Mb: 1280
    if (i2 < 1280) {
        int s = i2 >> 8;
        int j = i2 & 255;
        const float* pb = (s == 0) ? pb_phys : (s == 1) ? pb_obj :
                          (s == 2) ? pb_mine : (s == 3) ? pb_prog : pb_seq;
        float v;
        if (j < 64) {
            v = pb[j];
        } else {
            int jq = j - 64;
            float a = bqkv[jq];
            for (int k = 0; k < 64; k++)
                a = fmaf(Wqkv[jq * 64 + k], pb[k], a);
            v = a;
        }
        g_Mb[i2] = v;
        return;
    }
    int i3 = idx - 38144;                    // g_encT: 2560
    if (i3 < 2560) {
        float v;
        if (i3 < E_OBJ)        { int t = i3;          v = W_phys[(t & 63) * 29 + (t >> 6)]; }
        else if (i3 < E_MINE)  { int t = i3 - E_OBJ;  v = W_obj [(t & 31) * 15 + (t >> 5)]; }
        else if (i3 < E_PROG)  { int t = i3 - E_MINE; v = W_mine[(t & 15) *  8 + (t >> 4)]; }
        else if (i3 < E_SEQ)   { int t = i3 - E_PROG; v = W_prog[(t & 15) *  3 + (t >> 4)]; }
        else                   { int t = i3 - E_SEQ;  v = W_seq [(t & 15) *  3 + (t >> 4)]; }
        g_encT[i3] = v;
        return;
    }
    int i4 = idx - 40704;                    // g_WoT: 4096
    if (i4 < 4096) {
        int c = i4 >> 6, j = i4 & 63;
        g_WoT[i4] = Wo[j * 64 + c];
        return;
    }
    int i5 = idx - 44800;                    // g_WpT: 8192
    if (i5 < 8192) {
        int c = i5 >> 7, o = i5 & 127;
        g_WpT[i5] = Wp[o * 64 + c];
    }
}

// ---------------------------------------------------------------------------
template <int SOFF, int SDIM>
__device__ __forceinline__ void mgemm_seg4(const float* __restrict__ sM,
                                           const float* __restrict__ F0,
                                           float* acc, int j)
{
    const float* Ms = sM + SOFF * 256 + j;
    #pragma unroll
    for (int c = 0; c < SDIM; c += 4) {
        float w0 = Ms[(c + 0) * 256];
        float w1 = Ms[(c + 1) * 256];
        float w2 = Ms[(c + 2) * 256];
        float w3 = Ms[(c + 3) * 256];
        #pragma unroll
        for (int r = 0; r < 4; r++) {
            float4 f = *reinterpret_cast<const float4*>(F0 + r * 144 + SOFF + c);
            acc[r] = fmaf(f.x, w0, fmaf(f.y, w1, fmaf(f.z, w2, fmaf(f.w, w3, acc[r]))));
        }
    }
}

__global__ __launch_bounds__(NTHR, 1)
void fused_kernel(const float* __restrict__ x,
                  const float* __restrict__ b_phys, const float* __restrict__ b_obj,
                  const float* __restrict__ b_mine, const float* __restrict__ b_prog,
                  const float* __restrict__ b_seq,
                  const float* __restrict__ bo, const float* __restrict__ gamma,
                  const float* __restrict__ beta, const float* __restrict__ bp,
                  float* __restrict__ out)
{
    extern __shared__ float sm[];
    float* sM   = sm + OFF_M;
    float* sEnc = sm + OFF_ENC;
    float* sWo  = sm + OFF_WO;
    float* sMb  = sm + OFF_MB;
    float* sB   = sm + OFF_B;
    float* sX   = sm + OFF_X;
    float* sF   = sm + OFF_F;
    float* sY   = sm + OFF_Y;
    float* sP   = sm + OFF_P;

    const int tid = threadIdx.x;

    // ---- preload all weights into smem once per block ----
    for (int i = tid; i < 36864; i += NTHR) sM[i]   = g_M[i];
    for (int i = tid; i < 2560;  i += NTHR) sEnc[i] = g_encT[i];
    for (int i = tid; i < 4096;  i += NTHR) sWo[i]  = g_WoT[i];
    for (int i = tid; i < 1280;  i += NTHR) sMb[i]  = g_Mb[i];
    for (int i = tid; i < 464; i += NTHR) {
        float v;
        if (i < 64)       v = b_phys[i];
        else if (i < 96)  v = b_obj[i - 64];
        else if (i < 112) v = b_mine[i - 96];
        else if (i < 128) v = b_prog[i - 112];
        else if (i < 144) v = b_seq[i - 128];
        else if (i < 208) v = bo[i - 144];
        else if (i < 272) v = gamma[i - 208];
        else if (i < 336) v = beta[i - 272];
        else              v = bp[i - 336];
        sB[i] = v;
    }
    __syncthreads();

    for (int tile = blockIdx.x; tile < NTILES; tile += gridDim.x) {
        const int base = tile * RTILE;

        // ---- P0: load x tile (coalesced) ----
        if (tid < RTILE * 58) {
            int r = tid / 58, c = tid - r * 58;
            sX[r * 64 + c] = x[(size_t)base * 58 + tid];
        }
        __syncthreads();

        // ---- P1: encoders, thread-per-output ----
        {
            int r = tid >> 6, j = tid & 63;          // phys: 8 x 64 = 512
            const float* xr = sX + r * 64;
            float a = sB[j];
            #pragma unroll
            for (int c = 0; c < 29; c++)
                a = fmaf(sEnc[E_PHYS + c * 64 + j], xr[c], a);
            sF[r * 144 + j] = fmaxf(a, 0.f);
        }
        if (tid < 256) {                              // obj: 8 x 32
            int r = tid >> 5, j = tid & 31;
            const float* xr = sX + r * 64;
            float a = sB[64 + j];
            #pragma unroll
            for (int c = 0; c < 15; c++)
                a = fmaf(sEnc[E_OBJ + c * 32 + j], xr[29 + c], a);
            sF[r * 144 + 64 + j] = fmaxf(a, 0.f);
        }
        if (tid < 384) {                              // mine/prog/seq: 3 x 8 x 16
            int seg = tid >> 7;
            int t = tid & 127;
            int r = t >> 4, j = t & 15;
            const float* xr = sX + r * 64;
            const float* W; int xo, kk, oo;
            float a;
            if (seg == 0)      { W = sEnc + E_MINE; xo = 44; kk = 8; oo = 96;  a = sB[96 + j]; }
            else if (seg == 1) { W = sEnc + E_PROG; xo = 52; kk = 3; oo = 112; a = sB[112 + j]; }
            else               { W = sEnc + E_SEQ;  xo = 55; kk = 3; oo = 128; a = sB[128 + j]; }
            for (int c = 0; c < kk; c++)
                a = fmaf(W[c * 16 + j], xr[xo + c], a);
            sF[r * 144 + oo + j] = fmaxf(a, 0.f);
        }
        __syncthreads();

        // ---- P2: M-GEMM  Y[r][s][0:256] = tok|q|k|v ----
        {
            const int j  = tid & 255;
            const int g  = tid >> 8;        // 0,1 -> rows 4g..4g+3
            const float* F0 = sF + (g * 4) * 144;
            float* Y0 = sY + (g * 4) * YS;
            float acc[4];
            #pragma unroll
            for (int s = 0; s < 5; s++) {
                const float bias = sMb[s * 256 + j];
                #pragma unroll
                for (int r = 0; r < 4; r++) acc[r] = bias;
                switch (s) {
                    case 0:  mgemm_seg4<0,   64>(sM, F0, acc, j); break;
                    case 1:  mgemm_seg4<64,  32>(sM, F0, acc, j); break;
                    case 2:  mgemm_seg4<96,  16>(sM, F0, acc, j); break;
                    case 3:  mgemm_seg4<112, 16>(sM, F0, acc, j); break;
                    default: mgemm_seg4<128, 16>(sM, F0, acc, j); break;
                }
                // scatter j (0..255) into padded token slots: slot = j>>6, off = j&63
                const int slot = j >> 6, joff = j & 63;
                #pragma unroll
                for (int r = 0; r < 4; r++)
                    Y0[r * YS + s * TS + slot * 64 + joff] = acc[r];
            }
        }
        __syncthreads();

        // ---- P3: attention (160 units: row x head x query) ----
        if (tid < 160) {
            const int r  = tid & 7;
            const int hi = tid >> 3;
            const int h  = hi / 5;
            const int i  = hi - h * 5;
            float* Yr = sY + r * YS;
            const float4* q4 = reinterpret_cast<const float4*>(Yr + i * TS + 64 + h * 16);
            const float4 q0 = q4[0], q1 = q4[1], q2 = q4[2], q3 = q4[3];
            float sc[5];
            #pragma unroll
            for (int jt = 0; jt < 5; jt++) {
                const float4* k4 = reinterpret_cast<const float4*>(Yr + jt * TS + 128 + h * 16);
                float4 k0 = k4[0], k1 = k4[1], k2 = k4[2], k3 = k4[3];
                float d = q0.x * k0.x + q0.y * k0.y + q0.z * k0.z + q0.w * k0.w;
                d = fmaf(q1.x, k1.x, fmaf(q1.y, k1.y, fmaf(q1.z, k1.z, fmaf(q1.w, k1.w, d))));
                d = fmaf(q2.x, k2.x, fmaf(q2.y, k2.y, fmaf(q2.z, k2.z, fmaf(q2.w, k2.w, d))));
                d = fmaf(q3.x, k3.x, fmaf(q3.y, k3.y, fmaf(q3.z, k3.z, fmaf(q3.w, k3.w, d))));
                sc[jt] = d * 0.25f;
            }
            float mx = sc[0];
            #pragma unroll
            for (int jt = 1; jt < 5; jt++) mx = fmaxf(mx, sc[jt]);
            float sum = 0.f;
            #pragma unroll
            for (int jt = 0; jt < 5; jt++) { sc[jt] = __expf(sc[jt] - mx); sum += sc[jt]; }
            const float inv = 1.f / sum;
            #pragma unroll
            for (int tq = 0; tq < 4; tq++) {
                float4 c = make_float4(0.f, 0.f, 0.f, 0.f);
                #pragma unroll
                for (int jt = 0; jt < 5; jt++) {
                    const float4 v = reinterpret_cast<const float4*>(
                        Yr + jt * TS + 192 + h * 16)[tq];
                    c.x = fmaf(sc[jt], v.x, c.x);
                    c.y = fmaf(sc[jt], v.y, c.y);
                    c.z = fmaf(sc[jt], v.z, c.z);
                    c.w = fmaf(sc[jt], v.w, c.w);
                }
                c.x *= inv; c.y *= inv; c.z *= inv; c.w *= inv;
                reinterpret_cast<float4*>(Yr + i * TS + 64 + h * 16)[tq] = c;  // ctx->q slot
            }
        }
        __syncthreads();

        // ---- P4a: Wo projection + residual -> h (into k slot) ----
        {
            const int j = tid & 63;
            const int u = tid >> 6;          // row
            float* Yr = sY + u * YS;
            const float bov = sB[144 + j];
            float acc[5];
            #pragma unroll
            for (int s = 0; s < 5; s++) acc[s] = bov;
            #pragma unroll 4
            for (int c = 0; c < 64; c += 4) {
                float w0 = sWo[(c + 0) * 64 + j];
                float w1 = sWo[(c + 1) * 64 + j];
                float w2 = sWo[(c + 2) * 64 + j];
                float w3 = sWo[(c + 3) * 64 + j];
                #pragma unroll
                for (int s = 0; s < 5; s++) {
                    const float4 cv = *reinterpret_cast<const float4*>(Yr + s * TS + 64 + c);
                    acc[s] = fmaf(cv.x, w0, fmaf(cv.y, w1, fmaf(cv.z, w2, fmaf(cv.w, w3, acc[s]))));
                }
            }
            #pragma unroll
            for (int s = 0; s < 5; s++)
                Yr[s * TS + 128 + j] = Yr[s * TS + j] + acc[s];   // h = tok + proj
        }
        __syncthreads();

        // ---- P4b: LayerNorm + pool (warp per row) ----
        if (tid < 256) {
            const int r = tid >> 5, lane = tid & 31;
            const int j0 = lane * 2;
            float* Yr = sY + r * YS;
            const float g0 = sB[208 + j0], g1 = sB[208 + j0 + 1];
            const float be0 = sB[272 + j0], be1 = sB[272 + j0 + 1];
            float p0 = 0.f, p1 = 0.f;
            #pragma unroll
            for (int s = 0; s < 5; s++) {
                const float2 h2 = *reinterpret_cast<const float2*>(Yr + s * TS + 128 + j0);
                float sum = h2.x + h2.y;
                #pragma unroll
                for (int o = 16; o > 0; o >>= 1)
                    sum += __shfl_xor_sync(0xffffffff, sum, o);
                const float mu = sum * (1.f / 64.f);
                const float d0 = h2.x - mu, d1 = h2.y - mu;
                float v = d0 * d0 + d1 * d1;
                #pragma unroll
                for (int o = 16; o > 0; o >>= 1)
                    v += __shfl_xor_sync(0xffffffff, v, o);
                const float invstd = rsqrtf(v * (1.f / 64.f) + 1e-5f);
                p0 = fmaf(d0 * invstd, g0, p0 + be0);
                p1 = fmaf(d1 * invstd, g1, p1 + be1);
            }
            sP[r * 64 + j0]     = p0 * 0.2f;
            sP[r * 64 + j0 + 1] = p1 * 0.2f;
        }
        __syncthreads();

        // ---- P5: stage Wp into (dead) sY, then head GEMM ----
        {
            float4* dst = reinterpret_cast<float4*>(sY);
            const float4* src = reinterpret_cast<const float4*>(g_WpT);
            #pragma unroll
            for (int q = 0; q < 4; q++) dst[tid + q * NTHR] = src[tid + q * NTHR];
        }
        __syncthreads();
        {
            const int o  = tid & 127;
            const int r0 = (tid >> 7) * 2;           // rows r0, r0+1
            const float* sWp = sY;
            float a0 = sB[336 + o], a1 = a0;
            #pragma unroll 4
            for (int c = 0; c < 64; c += 4) {
                float w0 = sWp[(c + 0) * 128 + o];
                float w1 = sWp[(c + 1) * 128 + o];
                float w2 = sWp[(c + 2) * 128 + o];
                float w3 = sWp[(c + 3) * 128 + o];
                const float4 f0 = *reinterpret_cast<const float4*>(sP + r0 * 64 + c);
                const float4 f1 = *reinterpret_cast<const float4*>(sP + (r0 + 1) * 64 + c);
                a0 = fmaf(f0.x, w0, fmaf(f0.y, w1, fmaf(f0.z, w2, fmaf(f0.w, w3, a0))));
                a1 = fmaf(f1.x, w0, fmaf(f1.y, w1, fmaf(f1.z, w2, fmaf(f1.w, w3, a1))));
            }
            out[(size_t)(base + r0) * 128 + o]     = fmaxf(a0, 0.f);
            out[(size_t)(base + r0 + 1) * 128 + o] = fmaxf(a1, 0.f);
        }
        __syncthreads();
    }
}

// ---------------------------------------------------------------------------
extern "C" void kernel_launch(void* const* d_in, const int* in_sizes, int n_in,
                              void* d_out, int out_size)
{
    const float* x       = (const float*)d_in[0];
    const float* W_phys  = (const float*)d_in[1];
    const float* b_phys  = (const float*)d_in[2];
    const float* W_obj   = (const float*)d_in[3];
    const float* b_obj   = (const float*)d_in[4];
    const float* W_mine  = (const float*)d_in[5];
    const float* b_mine  = (const float*)d_in[6];
    const float* W_prog  = (const float*)d_in[7];
    const float* b_prog  = (const float*)d_in[8];
    const float* W_seq   = (const float*)d_in[9];
    const float* b_seq   = (const float*)d_in[10];
    const float* P_phys  = (const float*)d_in[11];
    const float* pb_phys = (const float*)d_in[12];
    const float* P_obj   = (const float*)d_in[13];
    const float* pb_obj  = (const float*)d_in[14];
    const float* P_mine  = (const float*)d_in[15];
    const float* pb_mine = (const float*)d_in[16];
    const float* P_prog  = (const float*)d_in[17];
    const float* pb_prog = (const float*)d_in[18];
    const float* P_seq   = (const float*)d_in[19];
    const float* pb_seq  = (const float*)d_in[20];
    const float* Wqkv    = (const float*)d_in[21];
    const float* bqkv    = (const float*)d_in[22];
    const float* Wo      = (const float*)d_in[23];
    const float* bo      = (const float*)d_in[24];
    const float* gamma   = (const float*)d_in[25];
    const float* beta    = (const float*)d_in[26];
    const float* Wp      = (const float*)d_in[27];
    const float* bp      = (const float*)d_in[28];
    float* out = (float*)d_out;

    cudaFuncSetAttribute(fused_kernel,
                         cudaFuncAttributeMaxDynamicSharedMemorySize,
                         SMEM_BYTES);

    int dev = 0, sms = 148;
    cudaGetDevice(&dev);
    cudaDeviceGetAttribute(&sms, cudaDevAttrMultiProcessorCount, dev);

    prep_kernel<<<207, 256>>>(Wqkv, bqkv,
                              P_phys, pb_phys, P_obj, pb_obj, P_mine, pb_mine,
                              P_prog, pb_prog, P_seq, pb_seq,
                              W_phys, W_obj, W_mine, W_prog, W_seq,
                              Wo, Wp);

    fused_kernel<<<sms, NTHR, SMEM_BYTES>>>(
        x, b_phys, b_obj, b_mine, b_prog, b_seq,
        bo, gamma, beta, bp, out);
}

// round 11
// speedup vs baseline: 1.1234x; 1.1201x over previous
#include <cuda_runtime.h>

// ---------------------------------------------------------------------------
// AttentiveStateMLP — two independent 256-thread groups per block (4 rows
// each, named barriers), deferred/batched head GEMM (KBUF tiles), x prefetch,
// Mb in registers. Attacks the ~40% barrier/serialization overhead seen at
// issue=40% / fma=23.6%.
// ---------------------------------------------------------------------------

#define NTILES4 32768                // 4-row tiles
#define NTHR    512
#define KBUF    4

// smem float offsets
#define OFF_M    0                   // 36864
#define OFF_ENC  36864               // 2560
#define OFF_WO   39424               // 4096
#define OFF_B    43520               // 464
#define GRP0     43984
#define GRP_SZ   7032                // Y 5200 | F 576 | PB 1024 | X 232
#define SMEM_FL  (GRP0 + 2*GRP_SZ)   // 58048
#define SMEM_BYTES (SMEM_FL*4)       // 232192 (<= 232448)

#define E_PHYS 0
#define E_OBJ  1856
#define E_MINE 2336
#define E_PROG 2464
#define E_SEQ  2512

__device__ float g_M[144 * 256];
__device__ float g_Mb[5 * 256];
__device__ float g_encT[2560];
__device__ float g_WoT[64 * 64];
__device__ float g_WpT[64 * 128];

__global__ void prep_kernel(
    const float* __restrict__ Wqkv, const float* __restrict__ bqkv,
    const float* __restrict__ P_phys, const float* __restrict__ pb_phys,
    const float* __restrict__ P_obj,  const float* __restrict__ pb_obj,
    const float* __restrict__ P_mine, const float* __restrict__ pb_mine,
    const float* __restrict__ P_prog, const float* __restrict__ pb_prog,
    const float* __restrict__ P_seq,  const float* __restrict__ pb_seq,
    const float* __restrict__ W_phys, const float* __restrict__ W_obj,
    const float* __restrict__ W_mine, const float* __restrict__ W_prog,
    const float* __restrict__ W_seq,
    const float* __restrict__ Wo, const float* __restrict__ Wp)
{
    int idx = blockIdx.x * blockDim.x + threadIdx.x;
    if (idx < 36864) {
        int cg = idx >> 8, j = idx & 255;
        const float* P; int dim, c;
        if (cg < 64)       { P = P_phys; dim = 64; c = cg; }
        else if (cg < 96)  { P = P_obj;  dim = 32; c = cg - 64; }
        else if (cg < 112) { P = P_mine; dim = 16; c = cg - 96; }
        else if (cg < 128) { P = P_prog; dim = 16; c = cg - 112; }
        else               { P = P_seq;  dim = 16; c = cg - 128; }
        float v;
        if (j < 64) v = P[j * dim + c];
        else {
            int jq = j - 64; float a = 0.f;
            for (int k = 0; k < 64; k++) a = fmaf(Wqkv[jq*64+k], P[k*dim+c], a);
            v = a;
        }
        g_M[idx] = v; return;
    }
    int i2 = idx - 36864;
    if (i2 < 1280) {
        int s = i2 >> 8, j = i2 & 255;
        const float* pb = (s==0)?pb_phys:(s==1)?pb_obj:(s==2)?pb_mine:(s==3)?pb_prog:pb_seq;
        float v;
        if (j < 64) v = pb[j];
        else {
            int jq = j - 64; float a = bqkv[jq];
            for (int k = 0; k < 64; k++) a = fmaf(Wqkv[jq*64+k], pb[k], a);
            v = a;
        }
        g_Mb[i2] = v; return;
    }
    int i3 = idx - 38144;
    if (i3 < 2560) {
        float v;
        if (i3 < E_OBJ)       { int t=i3;        v = W_phys[(t&63)*29 + (t>>6)]; }
        else if (i3 < E_MINE) { int t=i3-E_OBJ;  v = W_obj [(t&31)*15 + (t>>5)]; }
        else if (i3 < E_PROG) { int t=i3-E_MINE; v = W_mine[(t&15)* 8 + (t>>4)]; }
        else if (i3 < E_SEQ)  { int t=i3-E_PROG; v = W_prog[(t&15)* 3 + (t>>4)]; }
        else                  { int t=i3-E_SEQ;  v = W_seq [(t&15)* 3 + (t>>4)]; }
        g_encT[i3] = v; return;
    }
    int i4 = idx - 40704;
    if (i4 < 4096) { g_WoT[i4] = Wo[(i4&63)*64 + (i4>>6)]; return; }
    int i5 = idx - 44800;
    if (i5 < 8192) { g_WpT[i5] = Wp[(i5&127)*64 + (i5>>7)]; }
}

template <int SOFF, int SDIM>
__device__ __forceinline__ void mgemm_seg4(const float* __restrict__ sM,
                                           const float* __restrict__ F0,
                                           float* acc, int j)
{
    const float* Ms = sM + SOFF * 256 + j;
    #pragma unroll
    for (int c = 0; c < SDIM; c += 4) {
        float w0 = Ms[(c+0)*256], w1 = Ms[(c+1)*256];
        float w2 = Ms[(c+2)*256], w3 = Ms[(c+3)*256];
        #pragma unroll
        for (int r = 0; r < 4; r++) {
            float4 f = *reinterpret_cast<const float4*>(F0 + r*144 + SOFF + c);
            acc[r] = fmaf(f.x, w0, fmaf(f.y, w1, fmaf(f.z, w2, fmaf(f.w, w3, acc[r]))));
        }
    }
}

#define GBAR() asm volatile("bar.sync %0, 256;" :: "r"(gid + 1) : "memory")

__global__ __launch_bounds__(NTHR, 1)
void fused_kernel(const float* __restrict__ x,
                  const float* __restrict__ b_phys, const float* __restrict__ b_obj,
                  const float* __restrict__ b_mine, const float* __restrict__ b_prog,
                  const float* __restrict__ b_seq,
                  const float* __restrict__ bo, const float* __restrict__ gamma,
                  const float* __restrict__ beta, const float* __restrict__ bp,
                  float* __restrict__ out)
{
    extern __shared__ float sm[];
    float* sM   = sm + OFF_M;
    float* sEnc = sm + OFF_ENC;
    float* sWo  = sm + OFF_WO;
    float* sB   = sm + OFF_B;

    const int tid = threadIdx.x;
    const int gid = tid >> 8;        // group 0/1
    const int gt  = tid & 255;

    float* G   = sm + GRP0 + gid * GRP_SZ;
    float* gY  = G;                  // 4 x 1300 (token stride 260: tok|q|k|v|pad)
    float* gF  = G + 5200;           // 4 x 144
    float* gPB = G + 5776;           // pooled buf [c(64)][br(16)]
    float* gX  = G + 6800;           // 4 x 58

    // ---- block-wide weight preload ----
    for (int i = tid; i < 36864; i += NTHR) sM[i]   = g_M[i];
    for (int i = tid; i < 2560;  i += NTHR) sEnc[i] = g_encT[i];
    for (int i = tid; i < 4096;  i += NTHR) sWo[i]  = g_WoT[i];
    for (int i = tid; i < 464; i += NTHR) {
        float v;
        if (i < 64)       v = b_phys[i];
        else if (i < 96)  v = b_obj[i - 64];
        else if (i < 112) v = b_mine[i - 96];
        else if (i < 128) v = b_prog[i - 112];
        else if (i < 144) v = b_seq[i - 128];
        else if (i < 208) v = bo[i - 144];
        else if (i < 272) v = gamma[i - 208];
        else if (i < 336) v = beta[i - 272];
        else              v = bp[i - 336];
        sB[i] = v;
    }
    __syncthreads();

    float mb[5];
    #pragma unroll
    for (int s = 0; s < 5; s++) mb[s] = g_Mb[s * 256 + gt];

    const int tstep = gridDim.x * 2;
    int t = blockIdx.x * 2 + gid;
    if (t < NTILES4 && gt < 232) gX[gt] = x[(size_t)t * 232 + gt];
    GBAR();

    int nbuf = 0;
    int tb0  = t;

    for (; t < NTILES4; t += tstep) {
        // ---- P1: encoders ----
        {   int r = gt >> 6, j = gt & 63;
            const float* xr = gX + r * 58;
            float a = sB[j];
            #pragma unroll
            for (int c = 0; c < 29; c++) a = fmaf(sEnc[E_PHYS + c*64 + j], xr[c], a);
            gF[r*144 + j] = fmaxf(a, 0.f);
        }
        if (gt < 128) {
            int r = gt >> 5, j = gt & 31;
            const float* xr = gX + r * 58;
            float a = sB[64 + j];
            #pragma unroll
            for (int c = 0; c < 15; c++) a = fmaf(sEnc[E_OBJ + c*32 + j], xr[29+c], a);
            gF[r*144 + 64 + j] = fmaxf(a, 0.f);
        }
        if (gt < 192) {
            int seg = gt >> 6, r = (gt >> 4) & 3, j = gt & 15;
            const float* xr = gX + r * 58;
            const float* W; int xo, kk, oo; float a;
            if (seg == 0)      { W = sEnc+E_MINE; xo = 44; kk = 8; oo = 96;  a = sB[96+j]; }
            else if (seg == 1) { W = sEnc+E_PROG; xo = 52; kk = 3; oo = 112; a = sB[112+j]; }
            else               { W = sEnc+E_SEQ;  xo = 55; kk = 3; oo = 128; a = sB[128+j]; }
            for (int c = 0; c < kk; c++) a = fmaf(W[c*16 + j], xr[xo+c], a);
            gF[r*144 + oo + j] = fmaxf(a, 0.f);
        }
        GBAR();

        // ---- P2: M-GEMM (+ next-x prefetch) ----
        {
            const bool pf = (gt < 232) && (t + tstep < NTILES4);
            float pxv = 0.f;
            if (pf) pxv = x[(size_t)(t + tstep) * 232 + gt];

            const int j = gt;
            float acc[4];
            #pragma unroll
            for (int s = 0; s < 5; s++) {
                #pragma unroll
                for (int r = 0; r < 4; r++) acc[r] = mb[s];
                switch (s) {
                    case 0:  mgemm_seg4<0,   64>(sM, gF, acc, j); break;
                    case 1:  mgemm_seg4<64,  32>(sM, gF, acc, j); break;
                    case 2:  mgemm_seg4<96,  16>(sM, gF, acc, j); break;
                    case 3:  mgemm_seg4<112, 16>(sM, gF, acc, j); break;
                    default: mgemm_seg4<128, 16>(sM, gF, acc, j); break;
                }
                #pragma unroll
                for (int r = 0; r < 4; r++) gY[r*1300 + s*260 + j] = acc[r];
            }
            if (pf) gX[gt] = pxv;
        }
        GBAR();

        // ---- P3: attention (80 units: 4 rows x 4 heads x 5 queries) ----
        if (gt < 80) {
            const int r = gt / 20, u = gt - r*20;
            const int h = u / 5, i = u - h*5;
            float* Yr = gY + r * 1300;
            const float4* q4 = reinterpret_cast<const float4*>(Yr + i*260 + 64 + h*16);
            const float4 q0 = q4[0], q1 = q4[1], q2 = q4[2], q3 = q4[3];
            float sc[5];
            #pragma unroll
            for (int jt = 0; jt < 5; jt++) {
                const float4* k4 = reinterpret_cast<const float4*>(Yr + jt*260 + 128 + h*16);
                float4 k0 = k4[0], k1 = k4[1], k2 = k4[2], k3 = k4[3];
                float d = q0.x*k0.x + q0.y*k0.y + q0.z*k0.z + q0.w*k0.w;
                d = fmaf(q1.x,k1.x, fmaf(q1.y,k1.y, fmaf(q1.z,k1.z, fmaf(q1.w,k1.w, d))));
                d = fmaf(q2.x,k2.x, fmaf(q2.y,k2.y, fmaf(q2.z,k2.z, fmaf(q2.w,k2.w, d))));
                d = fmaf(q3.x,k3.x, fmaf(q3.y,k3.y, fmaf(q3.z,k3.z, fmaf(q3.w,k3.w, d))));
                sc[jt] = d * 0.25f;
            }
            float mx = sc[0];
            #pragma unroll
            for (int jt = 1; jt < 5; jt++) mx = fmaxf(mx, sc[jt]);
            float sum = 0.f;
            #pragma unroll
            for (int jt = 0; jt < 5; jt++) { sc[jt] = __expf(sc[jt] - mx); sum += sc[jt]; }
            const float inv = 1.f / sum;
            #pragma unroll
            for (int tq = 0; tq < 4; tq++) {
                float4 c = make_float4(0.f, 0.f, 0.f, 0.f);
                #pragma unroll
                for (int jt = 0; jt < 5; jt++) {
                    const float4 v = reinterpret_cast<const float4*>(Yr + jt*260 + 192 + h*16)[tq];
                    c.x = fmaf(sc[jt], v.x, c.x); c.y = fmaf(sc[jt], v.y, c.y);
                    c.z = fmaf(sc[jt], v.z, c.z); c.w = fmaf(sc[jt], v.w, c.w);
                }
                c.x *= inv; c.y *= inv; c.z *= inv; c.w *= inv;
                reinterpret_cast<float4*>(Yr + i*260 + 64 + h*16)[tq] = c;   // ctx -> q slot
            }
        }
        GBAR();

        // ---- P4a: Wo proj + residual -> h (k slot) ----
        {
            const int u = gt >> 6, j = gt & 63;
            float* Yr = gY + u * 1300;
            const float bov = sB[144 + j];
            float acc[5];
            #pragma unroll
            for (int s = 0; s < 5; s++) acc[s] = bov;
            #pragma unroll 4
            for (int c = 0; c < 64; c += 4) {
                float w0 = sWo[(c+0)*64 + j], w1 = sWo[(c+1)*64 + j];
                float w2 = sWo[(c+2)*64 + j], w3 = sWo[(c+3)*64 + j];
                #pragma unroll
                for (int s = 0; s < 5; s++) {
                    const float4 cv = *reinterpret_cast<const float4*>(Yr + s*260 + 64 + c);
                    acc[s] = fmaf(cv.x, w0, fmaf(cv.y, w1, fmaf(cv.z, w2, fmaf(cv.w, w3, acc[s]))));
                }
            }
            #pragma unroll
            for (int s = 0; s < 5; s++)
                Yr[s*260 + 128 + j] = Yr[s*260 + j] + acc[s];
        }
        GBAR();

        // ---- P4b: LayerNorm + pool -> PB ----
        if (gt < 128) {
            const int r = gt >> 5, lane = gt & 31, j0 = lane * 2;
            float* Yr = gY + r * 1300;
            const float g0 = sB[208+j0], g1 = sB[208+j0+1];
            const float be0 = sB[272+j0], be1 = sB[272+j0+1];
            float p0 = 0.f, p1 = 0.f;
            #pragma unroll
            for (int s = 0; s < 5; s++) {
                const float2 h2 = *reinterpret_cast<const float2*>(Yr + s*260 + 128 + j0);
                float sum = h2.x + h2.y;
                #pragma unroll
                for (int o = 16; o > 0; o >>= 1) sum += __shfl_xor_sync(0xffffffff, sum, o);
                const float mu = sum * (1.f/64.f);
                const float d0 = h2.x - mu, d1 = h2.y - mu;
                float v = d0*d0 + d1*d1;
                #pragma unroll
                for (int o = 16; o > 0; o >>= 1) v += __shfl_xor_sync(0xffffffff, v, o);
                const float invstd = rsqrtf(v * (1.f/64.f) + 1e-5f);
                p0 = fmaf(d0 * invstd, g0, p0 + be0);
                p1 = fmaf(d1 * invstd, g1, p1 + be1);
            }
            const int br = nbuf * 4 + r;
            gPB[j0*16 + br]     = p0 * 0.2f;
            gPB[(j0+1)*16 + br] = p1 * 0.2f;
        }
        nbuf++;

        const bool last = (t + tstep >= NTILES4);
        if (nbuf == KBUF || last) {
            GBAR();   // all Y reads done -> stage Wp into Y
            {   float4* d = reinterpret_cast<float4*>(gY);
                const float4* s4 = reinterpret_cast<const float4*>(g_WpT);
                #pragma unroll
                for (int q = 0; q < 4; q++) d[gt + q*256] = s4[gt + q*256];
            }
            GBAR();
            const int o = gt & 127, rh = gt >> 7;
            float a[8];
            const float bb = sB[336 + o];
            #pragma unroll
            for (int k = 0; k < 8; k++) a[k] = bb;
            #pragma unroll 4
            for (int c = 0; c < 32; c++) {
                const float wv = gY[c*128 + o];
                const float4 f0 = *reinterpret_cast<const float4*>(gPB + c*16 + rh*8);
                const float4 f1 = *reinterpret_cast<const float4*>(gPB + c*16 + rh*8 + 4);
                a[0]=fmaf(f0.x,wv,a[0]); a[1]=fmaf(f0.y,wv,a[1]);
                a[2]=fmaf(f0.z,wv,a[2]); a[3]=fmaf(f0.w,wv,a[3]);
                a[4]=fmaf(f1.x,wv,a[4]); a[5]=fmaf(f1.y,wv,a[5]);
                a[6]=fmaf(f1.z,wv,a[6]); a[7]=fmaf(f1.w,wv,a[7]);
            }
            GBAR();
            {   float4* d = reinterpret_cast<float4*>(gY);
                const float4* s4 = reinterpret_cast<const float4*>(g_WpT);
                #pragma unroll
                for (int q = 0; q < 4; q++) d[gt + q*256] = s4[1024 + gt + q*256];
            }
            GBAR();
            #pragma unroll 4
            for (int c = 0; c < 32; c++) {
                const float wv = gY[c*128 + o];
                const float4 f0 = *reinterpret_cast<const float4*>(gPB + (c+32)*16 + rh*8);
                const float4 f1 = *reinterpret_cast<const float4*>(gPB + (c+32)*16 + rh*8 + 4);
                a[0]=fmaf(f0.x,wv,a[0]); a[1]=fmaf(f0.y,wv,a[1]);
                a[2]=fmaf(f0.z,wv,a[2]); a[3]=fmaf(f0.w,wv,a[3]);
                a[4]=fmaf(f1.x,wv,a[4]); a[5]=fmaf(f1.y,wv,a[5]);
                a[6]=fmaf(f1.z,wv,a[6]); a[7]=fmaf(f1.w,wv,a[7]);
            }
            #pragma unroll
            for (int k = 0; k < 8; k++) {
                const int br = rh*8 + k, tb = br >> 2, r = br & 3;
                if (tb < nbuf)
                    out[(size_t)((tb0 + tb*tstep)*4 + r) * 128 + o] = fmaxf(a[k], 0.f);
            }
            nbuf = 0;
            tb0 = t + tstep;
        }
    }
}

// ---------------------------------------------------------------------------
extern "C" void kernel_launch(void* const* d_in, const int* in_sizes, int n_in,
                              void* d_out, int out_size)
{
    const float* x       = (const float*)d_in[0];
    const float* W_phys  = (const float*)d_in[1];
    const float* b_phys  = (const float*)d_in[2];
    const float* W_obj   = (const float*)d_in[3];
    const float* b_obj   = (const float*)d_in[4];
    const float* W_mine  = (const float*)d_in[5];
    const float* b_mine  = (const float*)d_in[6];
    const float* W_prog  = (const float*)d_in[7];
    const float* b_prog  = (const float*)d_in[8];
    const float* W_seq   = (const float*)d_in[9];
    const float* b_seq   = (const float*)d_in[10];
    const float* P_phys  = (const float*)d_in[11];
    const float* pb_phys = (const float*)d_in[12];
    const float* P_obj   = (const float*)d_in[13];
    const float* pb_obj  = (const float*)d_in[14];
    const float* P_mine  = (const float*)d_in[15];
    const float* pb_mine = (const float*)d_in[16];
    const float* P_prog  = (const float*)d_in[17];
    const float* pb_prog = (const float*)d_in[18];
    const float* P_seq   = (const float*)d_in[19];
    const float* pb_seq  = (const float*)d_in[20];
    const float* Wqkv    = (const float*)d_in[21];
    const float* bqkv    = (const float*)d_in[22];
    const float* Wo      = (const float*)d_in[23];
    const float* bo      = (const float*)d_in[24];
    const float* gamma   = (const float*)d_in[25];
    const float* beta    = (const float*)d_in[26];
    const float* Wp      = (const float*)d_in[27];
    const float* bp      = (const float*)d_in[28];
    float* out = (float*)d_out;

    cudaFuncSetAttribute(fused_kernel,
                         cudaFuncAttributeMaxDynamicSharedMemorySize, SMEM_BYTES);

    int dev = 0, sms = 148;
    cudaGetDevice(&dev);
    cudaDeviceGetAttribute(&sms, cudaDevAttrMultiProcessorCount, dev);

    prep_kernel<<<207, 256>>>(Wqkv, bqkv,
                              P_phys, pb_phys, P_obj, pb_obj, P_mine, pb_mine,
                              P_prog, pb_prog, P_seq, pb_seq,
                              W_phys, W_obj, W_mine, W_prog, W_seq,
                              Wo, Wp);

    fused_kernel<<<sms, NTHR, SMEM_BYTES>>>(
        x, b_phys, b_obj, b_mine, b_prog, b_seq,
        bo, gamma, beta, bp, out);
}

// round 12
// speedup vs baseline: 1.1454x; 1.0196x over previous
#include <cuda_runtime.h>

// ---------------------------------------------------------------------------
// AttentiveStateMLP — R12: R11 structure (two async 256-thread groups, named
// barriers, KBUF-batched head, x prefetch) + packed fma.rn.f32x2 arithmetic
// in the two biggest GEMM phases (P2 M-GEMM, P5 head GEMM). Features stored
// row-pair-packed so one LDS.128 broadcast feeds two FFMA2.
// ---------------------------------------------------------------------------

#define NTILES4 32768                // 4-row tiles
#define NTHR    512
#define KBUF    4

// smem float offsets
#define OFF_M    0                   // 36864
#define OFF_ENC  36864               // 2560
#define OFF_WO   39424               // 4096
#define OFF_B    43520               // 464
#define GRP0     43984
#define GRP_SZ   7032                // Y 5200 | F2 576 | PB 1024 | X 232
#define SMEM_FL  (GRP0 + 2*GRP_SZ)   // 58048
#define SMEM_BYTES (SMEM_FL*4)       // 232192 (<= 232448)

#define E_PHYS 0
#define E_OBJ  1856
#define E_MINE 2336
#define E_PROG 2464
#define E_SEQ  2512

__device__ float g_M[144 * 256];
__device__ float g_Mb[5 * 256];
__device__ float g_encT[2560];
__device__ float g_WoT[64 * 64];
__device__ float g_WpT[64 * 128];

__global__ void prep_kernel(
    const float* __restrict__ Wqkv, const float* __restrict__ bqkv,
    const float* __restrict__ P_phys, const float* __restrict__ pb_phys,
    const float* __restrict__ P_obj,  const float* __restrict__ pb_obj,
    const float* __restrict__ P_mine, const float* __restrict__ pb_mine,
    const float* __restrict__ P_prog, const float* __restrict__ pb_prog,
    const float* __restrict__ P_seq,  const float* __restrict__ pb_seq,
    const float* __restrict__ W_phys, const float* __restrict__ W_obj,
    const float* __restrict__ W_mine, const float* __restrict__ W_prog,
    const float* __restrict__ W_seq,
    const float* __restrict__ Wo, const float* __restrict__ Wp)
{
    int idx = blockIdx.x * blockDim.x + threadIdx.x;
    if (idx < 36864) {
        int cg = idx >> 8, j = idx & 255;
        const float* P; int dim, c;
        if (cg < 64)       { P = P_phys; dim = 64; c = cg; }
        else if (cg < 96)  { P = P_obj;  dim = 32; c = cg - 64; }
        else if (cg < 112) { P = P_mine; dim = 16; c = cg - 96; }
        else if (cg < 128) { P = P_prog; dim = 16; c = cg - 112; }
        else               { P = P_seq;  dim = 16; c = cg - 128; }
        float v;
        if (j < 64) v = P[j * dim + c];
        else {
            int jq = j - 64; float a = 0.f;
            for (int k = 0; k < 64; k++) a = fmaf(Wqkv[jq*64+k], P[k*dim+c], a);
            v = a;
        }
        g_M[idx] = v; return;
    }
    int i2 = idx - 36864;
    if (i2 < 1280) {
        int s = i2 >> 8, j = i2 & 255;
        const float* pb = (s==0)?pb_phys:(s==1)?pb_obj:(s==2)?pb_mine:(s==3)?pb_prog:pb_seq;
        float v;
        if (j < 64) v = pb[j];
        else {
            int jq = j - 64; float a = bqkv[jq];
            for (int k = 0; k < 64; k++) a = fmaf(Wqkv[jq*64+k], pb[k], a);
            v = a;
        }
        g_Mb[i2] = v; return;
    }
    int i3 = idx - 38144;
    if (i3 < 2560) {
        float v;
        if (i3 < E_OBJ)       { int t=i3;        v = W_phys[(t&63)*29 + (t>>6)]; }
        else if (i3 < E_MINE) { int t=i3-E_OBJ;  v = W_obj [(t&31)*15 + (t>>5)]; }
        else if (i3 < E_PROG) { int t=i3-E_MINE; v = W_mine[(t&15)* 8 + (t>>4)]; }
        else if (i3 < E_SEQ)  { int t=i3-E_PROG; v = W_prog[(t&15)* 3 + (t>>4)]; }
        else                  { int t=i3-E_SEQ;  v = W_seq [(t&15)* 3 + (t>>4)]; }
        g_encT[i3] = v; return;
    }
    int i4 = idx - 40704;
    if (i4 < 4096) { g_WoT[i4] = Wo[(i4&63)*64 + (i4>>6)]; return; }
    int i5 = idx - 44800;
    if (i5 < 8192) { g_WpT[i5] = Wp[(i5&127)*64 + (i5>>7)]; }
}

// ---- f32x2 packed helpers (sm_103a FFMA2 only reachable via PTX) ----
__device__ __forceinline__ unsigned long long dup2(float v) {
    unsigned long long r;
    asm("mov.b64 %0, {%1, %1};" : "=l"(r) : "f"(v));
    return r;
}
__device__ __forceinline__ void fma2(unsigned long long& d,
                                     unsigned long long a, unsigned long long b) {
    asm("fma.rn.f32x2 %0, %1, %2, %0;" : "+l"(d) : "l"(a), "l"(b));
}
__device__ __forceinline__ void unpk(unsigned long long p, float& lo, float& hi) {
    asm("mov.b64 {%0, %1}, %2;" : "=f"(lo), "=f"(hi) : "l"(p));
}

// P2 inner: packed row-pairs. F2 layout: pair p (rows 2p,2p+1): float2[c] at
// float offset p*288 + c*2. One LDS.128 = {f_r0[c],f_r1[c],f_r0[c+1],f_r1[c+1]}.
template <int SOFF, int SDIM>
__device__ __forceinline__ void mgemm2(const float* __restrict__ sM,
                                       const float* __restrict__ F2,
                                       unsigned long long& a0,
                                       unsigned long long& a1, int j)
{
    const float* Ms = sM + SOFF * 256 + j;
    const float* Fb = F2 + SOFF * 2;
    #pragma unroll
    for (int c = 0; c < SDIM; c += 2) {
        unsigned long long wd0 = dup2(Ms[(c+0)*256]);
        unsigned long long wd1 = dup2(Ms[(c+1)*256]);
        const ulonglong2 f0 = *reinterpret_cast<const ulonglong2*>(Fb + c*2);
        const ulonglong2 f1 = *reinterpret_cast<const ulonglong2*>(Fb + 288 + c*2);
        fma2(a0, f0.x, wd0); fma2(a0, f0.y, wd1);
        fma2(a1, f1.x, wd0); fma2(a1, f1.y, wd1);
    }
}

#define GBAR() asm volatile("bar.sync %0, 256;" :: "r"(gid + 1) : "memory")

__global__ __launch_bounds__(NTHR, 1)
void fused_kernel(const float* __restrict__ x,
                  const float* __restrict__ b_phys, const float* __restrict__ b_obj,
                  const float* __restrict__ b_mine, const float* __restrict__ b_prog,
                  const float* __restrict__ b_seq,
                  const float* __restrict__ bo, const float* __restrict__ gamma,
                  const float* __restrict__ beta, const float* __restrict__ bp,
                  float* __restrict__ out)
{
    extern __shared__ float sm[];
    float* sM   = sm + OFF_M;
    float* sEnc = sm + OFF_ENC;
    float* sWo  = sm + OFF_WO;
    float* sB   = sm + OFF_B;

    const int tid = threadIdx.x;
    const int gid = tid >> 8;        // group 0/1
    const int gt  = tid & 255;

    float* G   = sm + GRP0 + gid * GRP_SZ;
    float* gY  = G;                  // 4 x 1300 (token stride 260: tok|q|k|v|pad)
    float* gF2 = G + 5200;           // packed features: 2 pairs x 144 x 2
    float* gPB = G + 5776;           // pooled buf [c(64)][br(16)]
    float* gX  = G + 6800;           // 4 x 58

    // ---- block-wide weight preload ----
    for (int i = tid; i < 36864; i += NTHR) sM[i]   = g_M[i];
    for (int i = tid; i < 2560;  i += NTHR) sEnc[i] = g_encT[i];
    for (int i = tid; i < 4096;  i += NTHR) sWo[i]  = g_WoT[i];
    for (int i = tid; i < 464; i += NTHR) {
        float v;
        if (i < 64)       v = b_phys[i];
        else if (i < 96)  v = b_obj[i - 64];
        else if (i < 112) v = b_mine[i - 96];
        else if (i < 128) v = b_prog[i - 112];
        else if (i < 144) v = b_seq[i - 128];
        else if (i < 208) v = bo[i - 144];
        else if (i < 272) v = gamma[i - 208];
        else if (i < 336) v = beta[i - 272];
        else              v = bp[i - 336];
        sB[i] = v;
    }
    __syncthreads();

    float mb[5];
    #pragma unroll
    for (int s = 0; s < 5; s++) mb[s] = g_Mb[s * 256 + gt];

    const int tstep = gridDim.x * 2;
    int t = blockIdx.x * 2 + gid;
    if (t < NTILES4 && gt < 232) gX[gt] = x[(size_t)t * 232 + gt];
    GBAR();

    int nbuf = 0;
    int tb0  = t;

    for (; t < NTILES4; t += tstep) {
        // ---- P1: encoders -> packed F2 ----
        {   int r = gt >> 6, j = gt & 63;
            const float* xr = gX + r * 58;
            float a = sB[j];
            #pragma unroll
            for (int c = 0; c < 29; c++) a = fmaf(sEnc[E_PHYS + c*64 + j], xr[c], a);
            gF2[(r>>1)*288 + j*2 + (r&1)] = fmaxf(a, 0.f);
        }
        if (gt < 128) {
            int r = gt >> 5, j = gt & 31;
            const float* xr = gX + r * 58;
            float a = sB[64 + j];
            #pragma unroll
            for (int c = 0; c < 15; c++) a = fmaf(sEnc[E_OBJ + c*32 + j], xr[29+c], a);
            gF2[(r>>1)*288 + (64+j)*2 + (r&1)] = fmaxf(a, 0.f);
        }
        if (gt < 192) {
            int seg = gt >> 6, r = (gt >> 4) & 3, j = gt & 15;
            const float* xr = gX + r * 58;
            const float* W; int xo, kk, oo; float a;
            if (seg == 0)      { W = sEnc+E_MINE; xo = 44; kk = 8; oo = 96;  a = sB[96+j]; }
            else if (seg == 1) { W = sEnc+E_PROG; xo = 52; kk = 3; oo = 112; a = sB[112+j]; }
            else               { W = sEnc+E_SEQ;  xo = 55; kk = 3; oo = 128; a = sB[128+j]; }
            for (int c = 0; c < kk; c++) a = fmaf(W[c*16 + j], xr[xo+c], a);
            gF2[(r>>1)*288 + (oo+j)*2 + (r&1)] = fmaxf(a, 0.f);
        }
        GBAR();

        // ---- P2: M-GEMM, packed f32x2 (+ next-x prefetch) ----
        {
            const bool pf = (gt < 232) && (t + tstep < NTILES4);
            float pxv = 0.f;
            if (pf) pxv = x[(size_t)(t + tstep) * 232 + gt];

            const int j = gt;
            #pragma unroll
            for (int s = 0; s < 5; s++) {
                unsigned long long a0 = dup2(mb[s]);
                unsigned long long a1 = a0;
                switch (s) {
                    case 0:  mgemm2<0,   64>(sM, gF2, a0, a1, j); break;
                    case 1:  mgemm2<64,  32>(sM, gF2, a0, a1, j); break;
                    case 2:  mgemm2<96,  16>(sM, gF2, a0, a1, j); break;
                    case 3:  mgemm2<112, 16>(sM, gF2, a0, a1, j); break;
                    default: mgemm2<128, 16>(sM, gF2, a0, a1, j); break;
                }
                float r0, r1, r2, r3;
                unpk(a0, r0, r1); unpk(a1, r2, r3);
                gY[0*1300 + s*260 + j] = r0;
                gY[1*1300 + s*260 + j] = r1;
                gY[2*1300 + s*260 + j] = r2;
                gY[3*1300 + s*260 + j] = r3;
            }
            if (pf) gX[gt] = pxv;
        }
        GBAR();

        // ---- P3: attention (80 units: 4 rows x 4 heads x 5 queries) ----
        if (gt < 80) {
            const int r = gt / 20, u = gt - r*20;
            const int h = u / 5, i = u - h*5;
            float* Yr = gY + r * 1300;
            const float4* q4 = reinterpret_cast<const float4*>(Yr + i*260 + 64 + h*16);
            const float4 q0 = q4[0], q1 = q4[1], q2 = q4[2], q3 = q4[3];
            float sc[5];
            #pragma unroll
            for (int jt = 0; jt < 5; jt++) {
                const float4* k4 = reinterpret_cast<const float4*>(Yr + jt*260 + 128 + h*16);
                float4 k0 = k4[0], k1 = k4[1], k2 = k4[2], k3 = k4[3];
                float d = q0.x*k0.x + q0.y*k0.y + q0.z*k0.z + q0.w*k0.w;
                d = fmaf(q1.x,k1.x, fmaf(q1.y,k1.y, fmaf(q1.z,k1.z, fmaf(q1.w,k1.w, d))));
                d = fmaf(q2.x,k2.x, fmaf(q2.y,k2.y, fmaf(q2.z,k2.z, fmaf(q2.w,k2.w, d))));
                d = fmaf(q3.x,k3.x, fmaf(q3.y,k3.y, fmaf(q3.z,k3.z, fmaf(q3.w,k3.w, d))));
                sc[jt] = d * 0.25f;
            }
            float mx = sc[0];
            #pragma unroll
            for (int jt = 1; jt < 5; jt++) mx = fmaxf(mx, sc[jt]);
            float sum = 0.f;
            #pragma unroll
            for (int jt = 0; jt < 5; jt++) { sc[jt] = __expf(sc[jt] - mx); sum += sc[jt]; }
            const float inv = 1.f / sum;
            #pragma unroll
            for (int tq = 0; tq < 4; tq++) {
                float4 c = make_float4(0.f, 0.f, 0.f, 0.f);
                #pragma unroll
                for (int jt = 0; jt < 5; jt++) {
                    const float4 v = reinterpret_cast<const float4*>(Yr + jt*260 + 192 + h*16)[tq];
                    c.x = fmaf(sc[jt], v.x, c.x); c.y = fmaf(sc[jt], v.y, c.y);
                    c.z = fmaf(sc[jt], v.z, c.z); c.w = fmaf(sc[jt], v.w, c.w);
                }
                c.x *= inv; c.y *= inv; c.z *= inv; c.w *= inv;
                reinterpret_cast<float4*>(Yr + i*260 + 64 + h*16)[tq] = c;   // ctx -> q slot
            }
        }
        GBAR();

        // ---- P4a: Wo proj + residual -> h (k slot) ----
        {
            const int u = gt >> 6, j = gt & 63;
            float* Yr = gY + u * 1300;
            const float bov = sB[144 + j];
            float acc[5];
            #pragma unroll
            for (int s = 0; s < 5; s++) acc[s] = bov;
            #pragma unroll 4
            for (int c = 0; c < 64; c += 4) {
                float w0 = sWo[(c+0)*64 + j], w1 = sWo[(c+1)*64 + j];
                float w2 = sWo[(c+2)*64 + j], w3 = sWo[(c+3)*64 + j];
                #pragma unroll
                for (int s = 0; s < 5; s++) {
                    const float4 cv = *reinterpret_cast<const float4*>(Yr + s*260 + 64 + c);
                    acc[s] = fmaf(cv.x, w0, fmaf(cv.y, w1, fmaf(cv.z, w2, fmaf(cv.w, w3, acc[s]))));
                }
            }
            #pragma unroll
            for (int s = 0; s < 5; s++)
                Yr[s*260 + 128 + j] = Yr[s*260 + j] + acc[s];
        }
        GBAR();

        // ---- P4b: LayerNorm + pool -> PB ----
        if (gt < 128) {
            const int r = gt >> 5, lane = gt & 31, j0 = lane * 2;
            float* Yr = gY + r * 1300;
            const float g0 = sB[208+j0], g1 = sB[208+j0+1];
            const float be0 = sB[272+j0], be1 = sB[272+j0+1];
            float p0 = 0.f, p1 = 0.f;
            #pragma unroll
            for (int s = 0; s < 5; s++) {
                const float2 h2 = *reinterpret_cast<const float2*>(Yr + s*260 + 128 + j0);
                float sum = h2.x + h2.y;
                #pragma unroll
                for (int o = 16; o > 0; o >>= 1) sum += __shfl_xor_sync(0xffffffff, sum, o);
                const float mu = sum * (1.f/64.f);
                const float d0 = h2.x - mu, d1 = h2.y - mu;
                float v = d0*d0 + d1*d1;
                #pragma unroll
                for (int o = 16; o > 0; o >>= 1) v += __shfl_xor_sync(0xffffffff, v, o);
                const float invstd = rsqrtf(v * (1.f/64.f) + 1e-5f);
                p0 = fmaf(d0 * invstd, g0, p0 + be0);
                p1 = fmaf(d1 * invstd, g1, p1 + be1);
            }
            const int br = nbuf * 4 + r;
            gPB[j0*16 + br]     = p0 * 0.2f;
            gPB[(j0+1)*16 + br] = p1 * 0.2f;
        }
        nbuf++;

        const bool last = (t + tstep >= NTILES4);
        if (nbuf == KBUF || last) {
            GBAR();   // all Y reads done -> stage Wp into Y
            {   float4* d = reinterpret_cast<float4*>(gY);
                const float4* s4 = reinterpret_cast<const float4*>(g_WpT);
                #pragma unroll
                for (int q = 0; q < 4; q++) d[gt + q*256] = s4[gt + q*256];
            }
            GBAR();
            const int o = gt & 127, rh = gt >> 7;
            const float bb = sB[336 + o];
            unsigned long long a01 = dup2(bb), a23 = a01, a45 = a01, a67 = a01;
            #pragma unroll 4
            for (int c = 0; c < 32; c++) {
                const unsigned long long wd = dup2(gY[c*128 + o]);
                const ulonglong2 p0 = *reinterpret_cast<const ulonglong2*>(gPB + c*16 + rh*8);
                const ulonglong2 p1 = *reinterpret_cast<const ulonglong2*>(gPB + c*16 + rh*8 + 4);
                fma2(a01, p0.x, wd); fma2(a23, p0.y, wd);
                fma2(a45, p1.x, wd); fma2(a67, p1.y, wd);
            }
            GBAR();
            {   float4* d = reinterpret_cast<float4*>(gY);
                const float4* s4 = reinterpret_cast<const float4*>(g_WpT);
                #pragma unroll
                for (int q = 0; q < 4; q++) d[gt + q*256] = s4[1024 + gt + q*256];
            }
            GBAR();
            #pragma unroll 4
            for (int c = 0; c < 32; c++) {
                const unsigned long long wd = dup2(gY[c*128 + o]);
                const ulonglong2 p0 = *reinterpret_cast<const ulonglong2*>(gPB + (c+32)*16 + rh*8);
                const ulonglong2 p1 = *reinterpret_cast<const ulonglong2*>(gPB + (c+32)*16 + rh*8 + 4);
                fma2(a01, p0.x, wd); fma2(a23, p0.y, wd);
                fma2(a45, p1.x, wd); fma2(a67, p1.y, wd);
            }
            float av[8];
            unpk(a01, av[0], av[1]); unpk(a23, av[2], av[3]);
            unpk(a45, av[4], av[5]); unpk(a67, av[6], av[7]);
            #pragma unroll
            for (int k = 0; k < 8; k++) {
                const int br = rh*8 + k, tb = br >> 2, r = br & 3;
                if (tb < nbuf)
                    out[(size_t)((tb0 + tb*tstep)*4 + r) * 128 + o] = fmaxf(av[k], 0.f);
            }
            nbuf = 0;
            tb0 = t + tstep;
        }
    }
}

// ---------------------------------------------------------------------------
extern "C" void kernel_launch(void* const* d_in, const int* in_sizes, int n_in,
                              void* d_out, int out_size)
{
    const float* x       = (const float*)d_in[0];
    const float* W_phys  = (const float*)d_in[1];
    const float* b_phys  = (const float*)d_in[2];
    const float* W_obj   = (const float*)d_in[3];
    const float* b_obj   = (const float*)d_in[4];
    const float* W_mine  = (const float*)d_in[5];
    const float* b_mine  = (const float*)d_in[6];
    const float* W_prog  = (const float*)d_in[7];
    const float* b_prog  = (const float*)d_in[8];
    const float* W_seq   = (const float*)d_in[9];
    const float* b_seq   = (const float*)d_in[10];
    const float* P_phys  = (const float*)d_in[11];
    const float* pb_phys = (const float*)d_in[12];
    const float* P_obj   = (const float*)d_in[13];
    const float* pb_obj  = (const float*)d_in[14];
    const float* P_mine  = (const float*)d_in[15];
    const float* pb_mine = (const float*)d_in[16];
    const float* P_prog  = (const float*)d_in[17];
    const float* pb_prog = (const float*)d_in[18];
    const float* P_seq   = (const float*)d_in[19];
    const float* pb_seq  = (const float*)d_in[20];
    const float* Wqkv    = (const float*)d_in[21];
    const float* bqkv    = (const float*)d_in[22];
    const float* Wo      = (const float*)d_in[23];
    const float* bo      = (const float*)d_in[24];
    const float* gamma   = (const float*)d_in[25];
    const float* beta    = (const float*)d_in[26];
    const float* Wp      = (const float*)d_in[27];
    const float* bp      = (const float*)d_in[28];
    float* out = (float*)d_out;

    cudaFuncSetAttribute(fused_kernel,
                         cudaFuncAttributeMaxDynamicSharedMemorySize, SMEM_BYTES);

    int dev = 0, sms = 148;
    cudaGetDevice(&dev);
    cudaDeviceGetAttribute(&sms, cudaDevAttrMultiProcessorCount, dev);

    prep_kernel<<<207, 256>>>(Wqkv, bqkv,
                              P_phys, pb_phys, P_obj, pb_obj, P_mine, pb_mine,
                              P_prog, pb_prog, P_seq, pb_seq,
                              W_phys, W_obj, W_mine, W_prog, W_seq,
                              Wo, Wp);

    fused_kernel<<<sms, NTHR, SMEM_BYTES>>>(
        x, b_phys, b_obj, b_mine, b_prog, b_seq,
        bo, gamma, beta, bp, out);
}

// round 14
// speedup vs baseline: 1.2113x; 1.0576x over previous
#include <cuda_runtime.h>

// ---------------------------------------------------------------------------
// AttentiveStateMLP — R13: R12 skeleton (two async 256-thread groups, named
// barriers, KBUF-batched head, FFMA2 in P2/P5) + row-pair weight reuse in the
// two row-redundant phases: P1 encoders and P4a Wo-projection now use
// thread=(col,row-pair) so each weight LDS feeds 2 rows. x is pair-packed.
// Attacks the L1=91.9% smem-wavefront bound.
// ---------------------------------------------------------------------------

#define NTILES4 32768
#define NTHR    512
#define KBUF    4

#define OFF_M    0                   // 36864
#define OFF_ENC  36864               // 2560
#define OFF_WO   39424               // 4096
#define OFF_B    43520               // 464
#define GRP0     43984
#define GRP_SZ   7032                // Y 5200 | F2 576 | PB 1024 | X2 232
#define SMEM_FL  (GRP0 + 2*GRP_SZ)
#define SMEM_BYTES (SMEM_FL*4)       // 232192

#define E_PHYS 0
#define E_OBJ  1856
#define E_MINE 2336
#define E_PROG 2464
#define E_SEQ  2512

__device__ float g_M[144 * 256];
__device__ float g_Mb[5 * 256];
__device__ float g_encT[2560];
__device__ float g_WoT[64 * 64];
__device__ float g_WpT[64 * 128];

__global__ void prep_kernel(
    const float* __restrict__ Wqkv, const float* __restrict__ bqkv,
    const float* __restrict__ P_phys, const float* __restrict__ pb_phys,
    const float* __restrict__ P_obj,  const float* __restrict__ pb_obj,
    const float* __restrict__ P_mine, const float* __restrict__ pb_mine,
    const float* __restrict__ P_prog, const float* __restrict__ pb_prog,
    const float* __restrict__ P_seq,  const float* __restrict__ pb_seq,
    const float* __restrict__ W_phys, const float* __restrict__ W_obj,
    const float* __restrict__ W_mine, const float* __restrict__ W_prog,
    const float* __restrict__ W_seq,
    const float* __restrict__ Wo, const float* __restrict__ Wp)
{
    int idx = blockIdx.x * blockDim.x + threadIdx.x;
    if (idx < 36864) {
        int cg = idx >> 8, j = idx & 255;
        const float* P; int dim, c;
        if (cg < 64)       { P = P_phys; dim = 64; c = cg; }
        else if (cg < 96)  { P = P_obj;  dim = 32; c = cg - 64; }
        else if (cg < 112) { P = P_mine; dim = 16; c = cg - 96; }
        else if (cg < 128) { P = P_prog; dim = 16; c = cg - 112; }
        else               { P = P_seq;  dim = 16; c = cg - 128; }
        float v;
        if (j < 64) v = P[j * dim + c];
        else {
            int jq = j - 64; float a = 0.f;
            for (int k = 0; k < 64; k++) a = fmaf(Wqkv[jq*64+k], P[k*dim+c], a);
            v = a;
        }
        g_M[idx] = v; return;
    }
    int i2 = idx - 36864;
    if (i2 < 1280) {
        int s = i2 >> 8, j = i2 & 255;
        const float* pb = (s==0)?pb_phys:(s==1)?pb_obj:(s==2)?pb_mine:(s==3)?pb_prog:pb_seq;
        float v;
        if (j < 64) v = pb[j];
        else {
            int jq = j - 64; float a = bqkv[jq];
            for (int k = 0; k < 64; k++) a = fmaf(Wqkv[jq*64+k], pb[k], a);
            v = a;
        }
        g_Mb[i2] = v; return;
    }
    int i3 = idx - 38144;
    if (i3 < 2560) {
        float v;
        if (i3 < E_OBJ)       { int t=i3;        v = W_phys[(t&63)*29 + (t>>6)]; }
        else if (i3 < E_MINE) { int t=i3-E_OBJ;  v = W_obj [(t&31)*15 + (t>>5)]; }
        else if (i3 < E_PROG) { int t=i3-E_MINE; v = W_mine[(t&15)* 8 + (t>>4)]; }
        else if (i3 < E_SEQ)  { int t=i3-E_PROG; v = W_prog[(t&15)* 3 + (t>>4)]; }
        else                  { int t=i3-E_SEQ;  v = W_seq [(t&15)* 3 + (t>>4)]; }
        g_encT[i3] = v; return;
    }
    int i4 = idx - 40704;
    if (i4 < 4096) { g_WoT[i4] = Wo[(i4&63)*64 + (i4>>6)]; return; }
    int i5 = idx - 44800;
    if (i5 < 8192) { g_WpT[i5] = Wp[(i5&127)*64 + (i5>>7)]; }
}

__device__ __forceinline__ unsigned long long dup2(float v) {
    unsigned long long r;
    asm("mov.b64 %0, {%1, %1};" : "=l"(r) : "f"(v));
    return r;
}
__device__ __forceinline__ void fma2(unsigned long long& d,
                                     unsigned long long a, unsigned long long b) {
    asm("fma.rn.f32x2 %0, %1, %2, %0;" : "+l"(d) : "l"(a), "l"(b));
}
__device__ __forceinline__ void unpk(unsigned long long p, float& lo, float& hi) {
    asm("mov.b64 {%0, %1}, %2;" : "=f"(lo), "=f"(hi) : "l"(p));
}

template <int SOFF, int SDIM>
__device__ __forceinline__ void mgemm2(const float* __restrict__ sM,
                                       const float* __restrict__ F2,
                                       unsigned long long& a0,
                                       unsigned long long& a1, int j)
{
    const float* Ms = sM + SOFF * 256 + j;
    const float* Fb = F2 + SOFF * 2;
    #pragma unroll
    for (int c = 0; c < SDIM; c += 2) {
        unsigned long long wd0 = dup2(Ms[(c+0)*256]);
        unsigned long long wd1 = dup2(Ms[(c+1)*256]);
        const ulonglong2 f0 = *reinterpret_cast<const ulonglong2*>(Fb + c*2);
        const ulonglong2 f1 = *reinterpret_cast<const ulonglong2*>(Fb + 288 + c*2);
        fma2(a0, f0.x, wd0); fma2(a0, f0.y, wd1);
        fma2(a1, f1.x, wd0); fma2(a1, f1.y, wd1);
    }
}

#define GBAR() asm volatile("bar.sync %0, 256;" :: "r"(gid + 1) : "memory")

__global__ __launch_bounds__(NTHR, 1)
void fused_kernel(const float* __restrict__ x,
                  const float* __restrict__ b_phys, const float* __restrict__ b_obj,
                  const float* __restrict__ b_mine, const float* __restrict__ b_prog,
                  const float* __restrict__ b_seq,
                  const float* __restrict__ bo, const float* __restrict__ gamma,
                  const float* __restrict__ beta, const float* __restrict__ bp,
                  float* __restrict__ out)
{
    extern __shared__ float sm[];
    float* sM   = sm + OFF_M;
    float* sEnc = sm + OFF_ENC;
    float* sWo  = sm + OFF_WO;
    float* sB   = sm + OFF_B;

    const int tid = threadIdx.x;
    const int gid = tid >> 8;
    const int gt  = tid & 255;

    float* G   = sm + GRP0 + gid * GRP_SZ;
    float* gY  = G;                  // 4 x 1300 (token stride 260: tok|q|k|v|pad)
    float* gF2 = G + 5200;           // packed features: 2 pairs x 144 x 2
    float* gPB = G + 5776;           // pooled buf [c(64)][br(16)]
    float* gX  = G + 6800;           // packed x: [c(58)][pair(2)][2]

    for (int i = tid; i < 36864; i += NTHR) sM[i]   = g_M[i];
    for (int i = tid; i < 2560;  i += NTHR) sEnc[i] = g_encT[i];
    for (int i = tid; i < 4096;  i += NTHR) sWo[i]  = g_WoT[i];
    for (int i = tid; i < 464; i += NTHR) {
        float v;
        if (i < 64)       v = b_phys[i];
        else if (i < 96)  v = b_obj[i - 64];
        else if (i < 112) v = b_mine[i - 96];
        else if (i < 128) v = b_prog[i - 112];
        else if (i < 144) v = b_seq[i - 128];
        else if (i < 208) v = bo[i - 144];
        else if (i < 272) v = gamma[i - 208];
        else if (i < 336) v = beta[i - 272];
        else              v = bp[i - 336];
        sB[i] = v;
    }
    __syncthreads();

    float mb[5];
    #pragma unroll
    for (int s = 0; s < 5; s++) mb[s] = g_Mb[s * 256 + gt];

    const int tstep = gridDim.x * 2;
    int t = blockIdx.x * 2 + gid;
    if (t < NTILES4 && gt < 232) {
        int r = gt / 58, c = gt - r * 58;
        gX[c*4 + (r>>1)*2 + (r&1)] = x[(size_t)t * 232 + gt];
    }
    GBAR();

    int nbuf = 0;
    int tb0  = t;

    for (; t < NTILES4; t += tstep) {
        // ---- P1: encoders, thread=(col, row-pair), weight reused for 2 rows ----
        if (gt < 128) {
            const int p = gt >> 6, j = gt & 63;
            float a0 = sB[j], a1 = a0;
            #pragma unroll
            for (int c = 0; c < 29; c++) {
                const float w = sEnc[E_PHYS + c*64 + j];
                const float2 x2 = *reinterpret_cast<const float2*>(gX + c*4 + p*2);
                a0 = fmaf(w, x2.x, a0); a1 = fmaf(w, x2.y, a1);
            }
            *reinterpret_cast<float2*>(gF2 + p*288 + j*2) =
                make_float2(fmaxf(a0, 0.f), fmaxf(a1, 0.f));
            if (gt >= 96) {                       // seq: j=gt&15, p=(gt>>4)&1
                const int js = gt & 15, ps = (gt >> 4) & 1;
                float b0 = sB[128 + js], b1 = b0;
                #pragma unroll
                for (int c = 0; c < 3; c++) {
                    const float w = sEnc[E_SEQ + c*16 + js];
                    const float2 x2 = *reinterpret_cast<const float2*>(gX + (55+c)*4 + ps*2);
                    b0 = fmaf(w, x2.x, b0); b1 = fmaf(w, x2.y, b1);
                }
                *reinterpret_cast<float2*>(gF2 + ps*288 + (128+js)*2) =
                    make_float2(fmaxf(b0, 0.f), fmaxf(b1, 0.f));
            }
        } else if (gt < 192) {                    // obj
            const int p = (gt >> 5) & 1, j = gt & 31;
            float a0 = sB[64 + j], a1 = a0;
            #pragma unroll
            for (int c = 0; c < 15; c++) {
                const float w = sEnc[E_OBJ + c*32 + j];
                const float2 x2 = *reinterpret_cast<const float2*>(gX + (29+c)*4 + p*2);
                a0 = fmaf(w, x2.x, a0); a1 = fmaf(w, x2.y, a1);
            }
            *reinterpret_cast<float2*>(gF2 + p*288 + (64+j)*2) =
                make_float2(fmaxf(a0, 0.f), fmaxf(a1, 0.f));
        } else {                                  // mine (192..223), prog (224..255)
            const int p = (gt >> 4) & 1, j = gt & 15;
            const bool isMine = gt < 224;
            const float* W = isMine ? (sEnc + E_MINE) : (sEnc + E_PROG);
            const int xo = isMine ? 44 : 52, oo = isMine ? 96 : 112;
            const int kk = isMine ? 8 : 3;
            float a0 = sB[oo + j], a1 = a0;
            for (int c = 0; c < kk; c++) {
                const float w = W[c*16 + j];
                const float2 x2 = *reinterpret_cast<const float2*>(gX + (xo+c)*4 + p*2);
                a0 = fmaf(w, x2.x, a0); a1 = fmaf(w, x2.y, a1);
            }
            *reinterpret_cast<float2*>(gF2 + p*288 + (oo+j)*2) =
                make_float2(fmaxf(a0, 0.f), fmaxf(a1, 0.f));
        }
        GBAR();

        // ---- P2: M-GEMM, packed f32x2 (+ next-x prefetch, packed store) ----
        {
            const bool pf = (gt < 232) && (t + tstep < NTILES4);
            float pxv = 0.f;
            if (pf) pxv = x[(size_t)(t + tstep) * 232 + gt];

            const int j = gt;
            #pragma unroll
            for (int s = 0; s < 5; s++) {
                unsigned long long a0 = dup2(mb[s]);
                unsigned long long a1 = a0;
                switch (s) {
                    case 0:  mgemm2<0,   64>(sM, gF2, a0, a1, j); break;
                    case 1:  mgemm2<64,  32>(sM, gF2, a0, a1, j); break;
                    case 2:  mgemm2<96,  16>(sM, gF2, a0, a1, j); break;
                    case 3:  mgemm2<112, 16>(sM, gF2, a0, a1, j); break;
                    default: mgemm2<128, 16>(sM, gF2, a0, a1, j); break;
                }
                float r0, r1, r2, r3;
                unpk(a0, r0, r1); unpk(a1, r2, r3);
                gY[0*1300 + s*260 + j] = r0;
                gY[1*1300 + s*260 + j] = r1;
                gY[2*1300 + s*260 + j] = r2;
                gY[3*1300 + s*260 + j] = r3;
            }
            if (pf) {
                int r = gt / 58, c = gt - r * 58;
                gX[c*4 + (r>>1)*2 + (r&1)] = pxv;
            }
        }
        GBAR();

        // ---- P3: attention (80 units: 4 rows x 4 heads x 5 queries) ----
        if (gt < 80) {
            const int r = gt / 20, u = gt - r*20;
            const int h = u / 5, i = u - h*5;
            float* Yr = gY + r * 1300;
            const float4* q4 = reinterpret_cast<const float4*>(Yr + i*260 + 64 + h*16);
            const float4 q0 = q4[0], q1 = q4[1], q2 = q4[2], q3 = q4[3];
            float sc[5];
            #pragma unroll
            for (int jt = 0; jt < 5; jt++) {
                const float4* k4 = reinterpret_cast<const float4*>(Yr + jt*260 + 128 + h*16);
                float4 k0 = k4[0], k1 = k4[1], k2 = k4[2], k3 = k4[3];
                float d = q0.x*k0.x + q0.y*k0.y + q0.z*k0.z + q0.w*k0.w;
                d = fmaf(q1.x,k1.x, fmaf(q1.y,k1.y, fmaf(q1.z,k1.z, fmaf(q1.w,k1.w, d))));
                d = fmaf(q2.x,k2.x, fmaf(q2.y,k2.y, fmaf(q2.z,k2.z, fmaf(q2.w,k2.w, d))));
                d = fmaf(q3.x,k3.x, fmaf(q3.y,k3.y, fmaf(q3.z,k3.z, fmaf(q3.w,k3.w, d))));
                sc[jt] = d * 0.25f;
            }
            float mx = sc[0];
            #pragma unroll
            for (int jt = 1; jt < 5; jt++) mx = fmaxf(mx, sc[jt]);
            float sum = 0.f;
            #pragma unroll
            for (int jt = 0; jt < 5; jt++) { sc[jt] = __expf(sc[jt] - mx); sum += sc[jt]; }
            const float inv = 1.f / sum;
            #pragma unroll
            for (int tq = 0; tq < 4; tq++) {
                float4 c = make_float4(0.f, 0.f, 0.f, 0.f);
                #pragma unroll
                for (int jt = 0; jt < 5; jt++) {
                    const float4 v = reinterpret_cast<const float4*>(Yr + jt*260 + 192 + h*16)[tq];
                    c.x = fmaf(sc[jt], v.x, c.x); c.y = fmaf(sc[jt], v.y, c.y);
                    c.z = fmaf(sc[jt], v.z, c.z); c.w = fmaf(sc[jt], v.w, c.w);
                }
                c.x *= inv; c.y *= inv; c.z *= inv; c.w *= inv;
                reinterpret_cast<float4*>(Yr + i*260 + 64 + h*16)[tq] = c;   // ctx -> q slot
            }
        }
        GBAR();

        // ---- P4a: Wo proj + residual, thread=(j, pair): weight reused 2 rows ----
        if (gt < 128) {
            const int p = gt >> 6, j = gt & 63;
            float* Y0 = gY + (2*p)   * 1300;
            float* Y1 = gY + (2*p+1) * 1300;
            const float bov = sB[144 + j];
            float a0[5], a1[5];
            #pragma unroll
            for (int s = 0; s < 5; s++) { a0[s] = bov; a1[s] = bov; }
            #pragma unroll 4
            for (int c = 0; c < 64; c += 4) {
                const float w0 = sWo[(c+0)*64 + j], w1 = sWo[(c+1)*64 + j];
                const float w2 = sWo[(c+2)*64 + j], w3 = sWo[(c+3)*64 + j];
                #pragma unroll
                for (int s = 0; s < 5; s++) {
                    const float4 c0 = *reinterpret_cast<const float4*>(Y0 + s*260 + 64 + c);
                    const float4 c1 = *reinterpret_cast<const float4*>(Y1 + s*260 + 64 + c);
                    a0[s] = fmaf(c0.x, w0, fmaf(c0.y, w1, fmaf(c0.z, w2, fmaf(c0.w, w3, a0[s]))));
                    a1[s] = fmaf(c1.x, w0, fmaf(c1.y, w1, fmaf(c1.z, w2, fmaf(c1.w, w3, a1[s]))));
                }
            }
            #pragma unroll
            for (int s = 0; s < 5; s++) {
                Y0[s*260 + 128 + j] = Y0[s*260 + j] + a0[s];
                Y1[s*260 + 128 + j] = Y1[s*260 + j] + a1[s];
            }
        }
        GBAR();

        // ---- P4b: LayerNorm + pool -> PB ----
        if (gt < 128) {
            const int r = gt >> 5, lane = gt & 31, j0 = lane * 2;
            float* Yr = gY + r * 1300;
            const float g0 = sB[208+j0], g1 = sB[208+j0+1];
            const float be0 = sB[272+j0], be1 = sB[272+j0+1];
            float p0 = 0.f, p1 = 0.f;
            #pragma unroll
            for (int s = 0; s < 5; s++) {
                const float2 h2 = *reinterpret_cast<const float2*>(Yr + s*260 + 128 + j0);
                float sum = h2.x + h2.y;
                #pragma unroll
                for (int o = 16; o > 0; o >>= 1) sum += __shfl_xor_sync(0xffffffff, sum, o);
                const float mu = sum * (1.f/64.f);
                const float d0 = h2.x - mu, d1 = h2.y - mu;
                float v = d0*d0 + d1*d1;
                #pragma unroll
                for (int o = 16; o > 0; o >>= 1) v += __shfl_xor_sync(0xffffffff, v, o);
                const float invstd = rsqrtf(v * (1.f/64.f) + 1e-5f);
                p0 = fmaf(d0 * invstd, g0, p0 + be0);
                p1 = fmaf(d1 * invstd, g1, p1 + be1);
            }
            const int br = nbuf * 4 + r;
            gPB[j0*16 + br]     = p0 * 0.2f;
            gPB[(j0+1)*16 + br] = p1 * 0.2f;
        }
        nbuf++;

        const bool last = (t + tstep >= NTILES4);
        if (nbuf == KBUF || last) {
            GBAR();
            {   float4* d = reinterpret_cast<float4*>(gY);
                const float4* s4 = reinterpret_cast<const float4*>(g_WpT);
                #pragma unroll
                for (int q = 0; q < 4; q++) d[gt + q*256] = s4[gt + q*256];
            }
            GBAR();
            const int o = gt & 127, rh = gt >> 7;
            const float bb = sB[336 + o];
            unsigned long long a01 = dup2(bb), a23 = a01, a45 = a01, a67 = a01;
            #pragma unroll 4
            for (int c = 0; c < 32; c++) {
                const unsigned long long wd = dup2(gY[c*128 + o]);
                const ulonglong2 p0 = *reinterpret_cast<const ulonglong2*>(gPB + c*16 + rh*8);
                const ulonglong2 p1 = *reinterpret_cast<const ulonglong2*>(gPB + c*16 + rh*8 + 4);
                fma2(a01, p0.x, wd); fma2(a23, p0.y, wd);
                fma2(a45, p1.x, wd); fma2(a67, p1.y, wd);
            }
            GBAR();
            {   float4* d = reinterpret_cast<float4*>(gY);
                const float4* s4 = reinterpret_cast<const float4*>(g_WpT);
                #pragma unroll
                for (int q = 0; q < 4; q++) d[gt + q*256] = s4[1024 + gt + q*256];
            }
            GBAR();
            #pragma unroll 4
            for (int c = 0; c < 32; c++) {
                const unsigned long long wd = dup2(gY[c*128 + o]);
                const ulonglong2 p0 = *reinterpret_cast<const ulonglong2*>(gPB + (c+32)*16 + rh*8);
                const ulonglong2 p1 = *reinterpret_cast<const ulonglong2*>(gPB + (c+32)*16 + rh*8 + 4);
                fma2(a01, p0.x, wd); fma2(a23, p0.y, wd);
                fma2(a45, p1.x, wd); fma2(a67, p1.y, wd);
            }
            float av[8];
            unpk(a01, av[0], av[1]); unpk(a23, av[2], av[3]);
            unpk(a45, av[4], av[5]); unpk(a67, av[6], av[7]);
            #pragma unroll
            for (int k = 0; k < 8; k++) {
                const int br = rh*8 + k, tb = br >> 2, r = br & 3;
                if (tb < nbuf)
                    out[(size_t)((tb0 + tb*tstep)*4 + r) * 128 + o] = fmaxf(av[k], 0.f);
            }
            nbuf = 0;
            tb0 = t + tstep;
        }
    }
}

// ---------------------------------------------------------------------------
extern "C" void kernel_launch(void* const* d_in, const int* in_sizes, int n_in,
                              void* d_out, int out_size)
{
    const float* x       = (const float*)d_in[0];
    const float* W_phys  = (const float*)d_in[1];
    const float* b_phys  = (const float*)d_in[2];
    const float* W_obj   = (const float*)d_in[3];
    const float* b_obj   = (const float*)d_in[4];
    const float* W_mine  = (const float*)d_in[5];
    const float* b_mine  = (const float*)d_in[6];
    const float* W_prog  = (const float*)d_in[7];
    const float* b_prog  = (const float*)d_in[8];
    const float* W_seq   = (const float*)d_in[9];
    const float* b_seq   = (const float*)d_in[10];
    const float* P_phys  = (const float*)d_in[11];
    const float* pb_phys = (const float*)d_in[12];
    const float* P_obj   = (const float*)d_in[13];
    const float* pb_obj  = (const float*)d_in[14];
    const float* P_mine  = (const float*)d_in[15];
    const float* pb_mine = (const float*)d_in[16];
    const float* P_prog  = (const float*)d_in[17];
    const float* pb_prog = (const float*)d_in[18];
    const float* P_seq   = (const float*)d_in[19];
    const float* pb_seq  = (const float*)d_in[20];
    const float* Wqkv    = (const float*)d_in[21];
    const float* bqkv    = (const float*)d_in[22];
    const float* Wo      = (const float*)d_in[23];
    const float* bo      = (const float*)d_in[24];
    const float* gamma   = (const float*)d_in[25];
    const float* beta    = (const float*)d_in[26];
    const float* Wp      = (const float*)d_in[27];
    const float* bp      = (const float*)d_in[28];
    float* out = (float*)d_out;

    cudaFuncSetAttribute(fused_kernel,
                         cudaFuncAttributeMaxDynamicSharedMemorySize, SMEM_BYTES);

    int dev = 0, sms = 148;
    cudaGetDevice(&dev);
    cudaDeviceGetAttribute(&sms, cudaDevAttrMultiProcessorCount, dev);

    prep_kernel<<<207, 256>>>(Wqkv, bqkv,
                              P_phys, pb_phys, P_obj, pb_obj, P_mine, pb_mine,
                              P_prog, pb_prog, P_seq, pb_seq,
                              W_phys, W_obj, W_mine, W_prog, W_seq,
                              Wo, Wp);

    fused_kernel<<<sms, NTHR, SMEM_BYTES>>>(
        x, b_phys, b_obj, b_mine, b_prog, b_seq,
        bo, gamma, beta, bp, out);
}

// round 16
// speedup vs baseline: 1.3980x; 1.1541x over previous
#include <cuda_runtime.h>

// ---------------------------------------------------------------------------
// AttentiveStateMLP — R15: R13 skeleton (two async 256-thread groups, named
// barriers, KBUF-batched head, FFMA2, row-pair reuse in P1/P4a) with P2
// restructured: features quad-packed (float4 of 4 rows per k), 128 threads
// x 2 j-columns each (LDS.64 weights), idle half does the x prefetch.
// Halves P2's broadcast wavefronts and cuts P2 instructions ~40%.
// ---------------------------------------------------------------------------

#define NTILES4 32768
#define NTHR    512
#define KBUF    4

#define OFF_M    0                   // 36864
#define OFF_ENC  36864               // 2560
#define OFF_WO   39424               // 4096
#define OFF_B    43520               // 464
#define GRP0     43984
#define GRP_SZ   7032                // Y 5200 | F4 576 | PB 1024 | X2 232
#define SMEM_FL  (GRP0 + 2*GRP_SZ)
#define SMEM_BYTES (SMEM_FL*4)       // 232192

#define E_PHYS 0
#define E_OBJ  1856
#define E_MINE 2336
#define E_PROG 2464
#define E_SEQ  2512

__device__ float g_M[144 * 256];
__device__ float g_Mb[5 * 256];
__device__ float g_encT[2560];
__device__ float g_WoT[64 * 64];
__device__ float g_WpT[64 * 128];

__global__ void prep_kernel(
    const float* __restrict__ Wqkv, const float* __restrict__ bqkv,
    const float* __restrict__ P_phys, const float* __restrict__ pb_phys,
    const float* __restrict__ P_obj,  const float* __restrict__ pb_obj,
    const float* __restrict__ P_mine, const float* __restrict__ pb_mine,
    const float* __restrict__ P_prog, const float* __restrict__ pb_prog,
    const float* __restrict__ P_seq,  const float* __restrict__ pb_seq,
    const float* __restrict__ W_phys, const float* __restrict__ W_obj,
    const float* __restrict__ W_mine, const float* __restrict__ W_prog,
    const float* __restrict__ W_seq,
    const float* __restrict__ Wo, const float* __restrict__ Wp)
{
    int idx = blockIdx.x * blockDim.x + threadIdx.x;
    if (idx < 36864) {
        int cg = idx >> 8, j = idx & 255;
        const float* P; int dim, c;
        if (cg < 64)       { P = P_phys; dim = 64; c = cg; }
        else if (cg < 96)  { P = P_obj;  dim = 32; c = cg - 64; }
        else if (cg < 112) { P = P_mine; dim = 16; c = cg - 96; }
        else if (cg < 128) { P = P_prog; dim = 16; c = cg - 112; }
        else               { P = P_seq;  dim = 16; c = cg - 128; }
        float v;
        if (j < 64) v = P[j * dim + c];
        else {
            int jq = j - 64; float a = 0.f;
            for (int k = 0; k < 64; k++) a = fmaf(Wqkv[jq*64+k], P[k*dim+c], a);
            v = a;
        }
        g_M[idx] = v; return;
    }
    int i2 = idx - 36864;
    if (i2 < 1280) {
        int s = i2 >> 8, j = i2 & 255;
        const float* pb = (s==0)?pb_phys:(s==1)?pb_obj:(s==2)?pb_mine:(s==3)?pb_prog:pb_seq;
        float v;
        if (j < 64) v = pb[j];
        else {
            int jq = j - 64; float a = bqkv[jq];
            for (int k = 0; k < 64; k++) a = fmaf(Wqkv[jq*64+k], pb[k], a);
            v = a;
        }
        g_Mb[i2] = v; return;
    }
    int i3 = idx - 38144;
    if (i3 < 2560) {
        float v;
        if (i3 < E_OBJ)       { int t=i3;        v = W_phys[(t&63)*29 + (t>>6)]; }
        else if (i3 < E_MINE) { int t=i3-E_OBJ;  v = W_obj [(t&31)*15 + (t>>5)]; }
        else if (i3 < E_PROG) { int t=i3-E_MINE; v = W_mine[(t&15)* 8 + (t>>4)]; }
        else if (i3 < E_SEQ)  { int t=i3-E_PROG; v = W_prog[(t&15)* 3 + (t>>4)]; }
        else                  { int t=i3-E_SEQ;  v = W_seq [(t&15)* 3 + (t>>4)]; }
        g_encT[i3] = v; return;
    }
    int i4 = idx - 40704;
    if (i4 < 4096) { g_WoT[i4] = Wo[(i4&63)*64 + (i4>>6)]; return; }
    int i5 = idx - 44800;
    if (i5 < 8192) { g_WpT[i5] = Wp[(i5&127)*64 + (i5>>7)]; }
}

__device__ __forceinline__ unsigned long long dup2(float v) {
    unsigned long long r;
    asm("mov.b64 %0, {%1, %1};" : "=l"(r) : "f"(v));
    return r;
}
__device__ __forceinline__ void fma2(unsigned long long& d,
                                     unsigned long long a, unsigned long long b) {
    asm("fma.rn.f32x2 %0, %1, %2, %0;" : "+l"(d) : "l"(a), "l"(b));
}
__device__ __forceinline__ void unpk(unsigned long long p, float& lo, float& hi) {
    asm("mov.b64 {%0, %1}, %2;" : "=f"(lo), "=f"(hi) : "l"(p));
}

// P2 inner: F4 quad-packed per k: float4{r0,r1,r2,r3} at F4 + k*4.
// Thread owns columns j0, j0+1. Per k: 1 LDS.64 (w pair) + 1 LDS.128 (f).
// a00=(r0,r1)@j0  a01=(r2,r3)@j0  a10=(r0,r1)@j1  a11=(r2,r3)@j1
template <int SOFF, int SDIM>
__device__ __forceinline__ void mgemm4(const float* __restrict__ sM,
                                       const float* __restrict__ F4,
                                       unsigned long long& a00,
                                       unsigned long long& a01,
                                       unsigned long long& a10,
                                       unsigned long long& a11, int j0)
{
    const float* Ms = sM + SOFF * 256 + j0;
    const float* Fb = F4 + SOFF * 4;
    #pragma unroll
    for (int c = 0; c < SDIM; c++) {
        const float2 w = *reinterpret_cast<const float2*>(Ms + c*256);
        const unsigned long long wd0 = dup2(w.x);
        const unsigned long long wd1 = dup2(w.y);
        const ulonglong2 f = *reinterpret_cast<const ulonglong2*>(Fb + c*4);
        fma2(a00, f.x, wd0); fma2(a01, f.y, wd0);
        fma2(a10, f.x, wd1); fma2(a11, f.y, wd1);
    }
}

#define GBAR() asm volatile("bar.sync %0, 256;" :: "r"(gid + 1) : "memory")

__global__ __launch_bounds__(NTHR, 1)
void fused_kernel(const float* __restrict__ x,
                  const float* __restrict__ b_phys, const float* __restrict__ b_obj,
                  const float* __restrict__ b_mine, const float* __restrict__ b_prog,
                  const float* __restrict__ b_seq,
                  const float* __restrict__ bo, const float* __restrict__ gamma,
                  const float* __restrict__ beta, const float* __restrict__ bp,
                  float* __restrict__ out)
{
    extern __shared__ float sm[];
    float* sM   = sm + OFF_M;
    float* sEnc = sm + OFF_ENC;
    float* sWo  = sm + OFF_WO;
    float* sB   = sm + OFF_B;

    const int tid = threadIdx.x;
    const int gid = tid >> 8;
    const int gt  = tid & 255;

    float* G   = sm + GRP0 + gid * GRP_SZ;
    float* gY  = G;                  // 4 x 1300 (token stride 260: tok|q/ctx|k/h|v|pad)
    float* gF4 = G + 5200;           // quad-packed features: [k(144)][r(4)]
    float* gPB = G + 5776;           // pooled buf [c(64)][br(16)]
    float* gX  = G + 6800;           // packed x: [c(58)][pair(2)][2]

    for (int i = tid; i < 36864; i += NTHR) sM[i]   = g_M[i];
    for (int i = tid; i < 2560;  i += NTHR) sEnc[i] = g_encT[i];
    for (int i = tid; i < 4096;  i += NTHR) sWo[i]  = g_WoT[i];
    for (int i = tid; i < 464; i += NTHR) {
        float v;
        if (i < 64)       v = b_phys[i];
        else if (i < 96)  v = b_obj[i - 64];
        else if (i < 112) v = b_mine[i - 96];
        else if (i < 128) v = b_prog[i - 112];
        else if (i < 144) v = b_seq[i - 128];
        else if (i < 208) v = bo[i - 144];
        else if (i < 272) v = gamma[i - 208];
        else if (i < 336) v = beta[i - 272];
        else              v = bp[i - 336];
        sB[i] = v;
    }
    __syncthreads();

    // per-thread M biases for the 2 owned columns (compute threads only)
    const int j0 = (gt < 128) ? (gt * 2) : 0;
    float mbA[5], mbB[5];
    #pragma unroll
    for (int s = 0; s < 5; s++) {
        mbA[s] = g_Mb[s * 256 + j0];
        mbB[s] = g_Mb[s * 256 + j0 + 1];
    }

    const int tstep = gridDim.x * 2;
    int t = blockIdx.x * 2 + gid;
    if (t < NTILES4 && gt < 232) {
        int r = gt / 58, c = gt - r * 58;
        gX[c*4 + (r>>1)*2 + (r&1)] = x[(size_t)t * 232 + gt];
    }
    GBAR();

    int nbuf = 0;
    int tb0  = t;

    for (; t < NTILES4; t += tstep) {
        // ---- P1: encoders, thread=(col, row-pair); quad-packed feature store ----
        if (gt < 128) {
            const int p = gt >> 6, j = gt & 63;
            float a0 = sB[j], a1 = a0;
            #pragma unroll
            for (int c = 0; c < 29; c++) {
                const float w = sEnc[E_PHYS + c*64 + j];
                const float2 x2 = *reinterpret_cast<const float2*>(gX + c*4 + p*2);
                a0 = fmaf(w, x2.x, a0); a1 = fmaf(w, x2.y, a1);
            }
            *reinterpret_cast<float2*>(gF4 + j*4 + p*2) =
                make_float2(fmaxf(a0, 0.f), fmaxf(a1, 0.f));
            if (gt >= 96) {                       // seq
                const int js = gt & 15, ps = (gt >> 4) & 1;
                float b0 = sB[128 + js], b1 = b0;
                #pragma unroll
                for (int c = 0; c < 3; c++) {
                    const float w = sEnc[E_SEQ + c*16 + js];
                    const float2 x2 = *reinterpret_cast<const float2*>(gX + (55+c)*4 + ps*2);
                    b0 = fmaf(w, x2.x, b0); b1 = fmaf(w, x2.y, b1);
                }
                *reinterpret_cast<float2*>(gF4 + (128+js)*4 + ps*2) =
                    make_float2(fmaxf(b0, 0.f), fmaxf(b1, 0.f));
            }
        } else if (gt < 192) {                    // obj
            const int p = (gt >> 5) & 1, j = gt & 31;
            float a0 = sB[64 + j], a1 = a0;
            #pragma unroll
            for (int c = 0; c < 15; c++) {
                const float w = sEnc[E_OBJ + c*32 + j];
                const float2 x2 = *reinterpret_cast<const float2*>(gX + (29+c)*4 + p*2);
                a0 = fmaf(w, x2.x, a0); a1 = fmaf(w, x2.y, a1);
            }
            *reinterpret_cast<float2*>(gF4 + (64+j)*4 + p*2) =
                make_float2(fmaxf(a0, 0.f), fmaxf(a1, 0.f));
        } else {                                  // mine (192..223), prog (224..255)
            const int p = (gt >> 4) & 1, j = gt & 15;
            const bool isMine = gt < 224;
            const float* W = isMine ? (sEnc + E_MINE) : (sEnc + E_PROG);
            const int xo = isMine ? 44 : 52, oo = isMine ? 96 : 112;
            const int kk = isMine ? 8 : 3;
            float a0 = sB[oo + j], a1 = a0;
            for (int c = 0; c < kk; c++) {
                const float w = W[c*16 + j];
                const float2 x2 = *reinterpret_cast<const float2*>(gX + (xo+c)*4 + p*2);
                a0 = fmaf(w, x2.x, a0); a1 = fmaf(w, x2.y, a1);
            }
            *reinterpret_cast<float2*>(gF4 + (oo+j)*4 + p*2) =
                make_float2(fmaxf(a0, 0.f), fmaxf(a1, 0.f));
        }
        GBAR();

        // ---- P2: M-GEMM on 128 threads (2 cols each); other half prefetches x ----
        if (gt < 128) {
            #pragma unroll
            for (int s = 0; s < 5; s++) {
                unsigned long long a00 = dup2(mbA[s]);
                unsigned long long a01 = a00;
                unsigned long long a10 = dup2(mbB[s]);
                unsigned long long a11 = a10;
                switch (s) {
                    case 0:  mgemm4<0,   64>(sM, gF4, a00, a01, a10, a11, j0); break;
                    case 1:  mgemm4<64,  32>(sM, gF4, a00, a01, a10, a11, j0); break;
                    case 2:  mgemm4<96,  16>(sM, gF4, a00, a01, a10, a11, j0); break;
                    case 3:  mgemm4<112, 16>(sM, gF4, a00, a01, a10, a11, j0); break;
                    default: mgemm4<128, 16>(sM, gF4, a00, a01, a10, a11, j0); break;
                }
                float r0a, r1a, r2a, r3a, r0b, r1b, r2b, r3b;
                unpk(a00, r0a, r1a); unpk(a01, r2a, r3a);
                unpk(a10, r0b, r1b); unpk(a11, r2b, r3b);
                float* Ys = gY + s*260 + j0;
                *reinterpret_cast<float2*>(Ys)          = make_float2(r0a, r0b);
                *reinterpret_cast<float2*>(Ys + 1300)   = make_float2(r1a, r1b);
                *reinterpret_cast<float2*>(Ys + 2600)   = make_float2(r2a, r2b);
                *reinterpret_cast<float2*>(Ys + 3900)   = make_float2(r3a, r3b);
            }
        } else if (t + tstep < NTILES4) {
            const int i0 = gt - 128;
            #pragma unroll
            for (int q = 0; q < 2; q++) {
                const int i = i0 + q*128;
                if (i < 232) {
                    const int r = i / 58, c = i - r*58;
                    gX[c*4 + (r>>1)*2 + (r&1)] = x[(size_t)(t + tstep) * 232 + i];
                }
            }
        }
        GBAR();

        // ---- P3: attention (80 units: 4 rows x 4 heads x 5 queries) ----
        if (gt < 80) {
            const int r = gt / 20, u = gt - r*20;
            const int h = u / 5, i = u - h*5;
            float* Yr = gY + r * 1300;
            const float4* q4 = reinterpret_cast<const float4*>(Yr + i*260 + 64 + h*16);
            const float4 q0 = q4[0], q1 = q4[1], q2 = q4[2], q3 = q4[3];
            float sc[5];
            #pragma unroll
            for (int jt = 0; jt < 5; jt++) {
                const float4* k4 = reinterpret_cast<const float4*>(Yr + jt*260 + 128 + h*16);
                float4 k0 = k4[0], k1 = k4[1], k2 = k4[2], k3 = k4[3];
                float d = q0.x*k0.x + q0.y*k0.y + q0.z*k0.z + q0.w*k0.w;
                d = fmaf(q1.x,k1.x, fmaf(q1.y,k1.y, fmaf(q1.z,k1.z, fmaf(q1.w,k1.w, d))));
                d = fmaf(q2.x,k2.x, fmaf(q2.y,k2.y, fmaf(q2.z,k2.z, fmaf(q2.w,k2.w, d))));
                d = fmaf(q3.x,k3.x, fmaf(q3.y,k3.y, fmaf(q3.z,k3.z, fmaf(q3.w,k3.w, d))));
                sc[jt] = d * 0.25f;
            }
            float mx = sc[0];
            #pragma unroll
            for (int jt = 1; jt < 5; jt++) mx = fmaxf(mx, sc[jt]);
            float sum = 0.f;
            #pragma unroll
            for (int jt = 0; jt < 5; jt++) { sc[jt] = __expf(sc[jt] - mx); sum += sc[jt]; }
            const float inv = 1.f / sum;
            #pragma unroll
            for (int tq = 0; tq < 4; tq++) {
                float4 c = make_float4(0.f, 0.f, 0.f, 0.f);
                #pragma unroll
                for (int jt = 0; jt < 5; jt++) {
                    const float4 v = reinterpret_cast<const float4*>(Yr + jt*260 + 192 + h*16)[tq];
                    c.x = fmaf(sc[jt], v.x, c.x); c.y = fmaf(sc[jt], v.y, c.y);
                    c.z = fmaf(sc[jt], v.z, c.z); c.w = fmaf(sc[jt], v.w, c.w);
                }
                c.x *= inv; c.y *= inv; c.z *= inv; c.w *= inv;
                reinterpret_cast<float4*>(Yr + i*260 + 64 + h*16)[tq] = c;   // ctx -> q slot
            }
        }
        GBAR();

        // ---- P4a: Wo proj + residual, thread=(j, pair): weight reused 2 rows ----
        if (gt < 128) {
            const int p = gt >> 6, j = gt & 63;
            float* Y0 = gY + (2*p)   * 1300;
            float* Y1 = gY + (2*p+1) * 1300;
            const float bov = sB[144 + j];
            float a0[5], a1[5];
            #pragma unroll
            for (int s = 0; s < 5; s++) { a0[s] = bov; a1[s] = bov; }
            #pragma unroll 4
            for (int c = 0; c < 64; c += 4) {
                const float w0 = sWo[(c+0)*64 + j], w1 = sWo[(c+1)*64 + j];
                const float w2 = sWo[(c+2)*64 + j], w3 = sWo[(c+3)*64 + j];
                #pragma unroll
                for (int s = 0; s < 5; s++) {
                    const float4 c0 = *reinterpret_cast<const float4*>(Y0 + s*260 + 64 + c);
                    const float4 c1 = *reinterpret_cast<const float4*>(Y1 + s*260 + 64 + c);
                    a0[s] = fmaf(c0.x, w0, fmaf(c0.y, w1, fmaf(c0.z, w2, fmaf(c0.w, w3, a0[s]))));
                    a1[s] = fmaf(c1.x, w0, fmaf(c1.y, w1, fmaf(c1.z, w2, fmaf(c1.w, w3, a1[s]))));
                }
            }
            #pragma unroll
            for (int s = 0; s < 5; s++) {
                Y0[s*260 + 128 + j] = Y0[s*260 + j] + a0[s];
                Y1[s*260 + 128 + j] = Y1[s*260 + j] + a1[s];
            }
        }
        GBAR();

        // ---- P4b: LayerNorm + pool -> PB ----
        if (gt < 128) {
            const int r = gt >> 5, lane = gt & 31, jj = lane * 2;
            float* Yr = gY + r * 1300;
            const float g0 = sB[208+jj], g1 = sB[208+jj+1];
            const float be0 = sB[272+jj], be1 = sB[272+jj+1];
            float p0 = 0.f, p1 = 0.f;
            #pragma unroll
            for (int s = 0; s < 5; s++) {
                const float2 h2 = *reinterpret_cast<const float2*>(Yr + s*260 + 128 + jj);
                float sum = h2.x + h2.y;
                #pragma unroll
                for (int o = 16; o > 0; o >>= 1) sum += __shfl_xor_sync(0xffffffff, sum, o);
                const float mu = sum * (1.f/64.f);
                const float d0 = h2.x - mu, d1 = h2.y - mu;
                float v = d0*d0 + d1*d1;
                #pragma unroll
                for (int o = 16; o > 0; o >>= 1) v += __shfl_xor_sync(0xffffffff, v, o);
                const float invstd = rsqrtf(v * (1.f/64.f) + 1e-5f);
                p0 = fmaf(d0 * invstd, g0, p0 + be0);
                p1 = fmaf(d1 * invstd, g1, p1 + be1);
            }
            const int br = nbuf * 4 + r;
            gPB[jj*16 + br]     = p0 * 0.2f;
            gPB[(jj+1)*16 + br] = p1 * 0.2f;
        }
        nbuf++;

        const bool last = (t + tstep >= NTILES4);
        if (nbuf == KBUF || last) {
            GBAR();
            {   float4* d = reinterpret_cast<float4*>(gY);
                const float4* s4 = reinterpret_cast<const float4*>(g_WpT);
                #pragma unroll
                for (int q = 0; q < 4; q++) d[gt + q*256] = s4[gt + q*256];
            }
            GBAR();
            const int o = gt & 127, rh = gt >> 7;
            const float bb = sB[336 + o];
            unsigned long long a01 = dup2(bb), a23 = a01, a45 = a01, a67 = a01;
            #pragma unroll 4
            for (int c = 0; c < 32; c++) {
                const unsigned long long wd = dup2(gY[c*128 + o]);
                const ulonglong2 p0 = *reinterpret_cast<const ulonglong2*>(gPB + c*16 + rh*8);
                const ulonglong2 p1 = *reinterpret_cast<const ulonglong2*>(gPB + c*16 + rh*8 + 4);
                fma2(a01, p0.x, wd); fma2(a23, p0.y, wd);
                fma2(a45, p1.x, wd); fma2(a67, p1.y, wd);
            }
            GBAR();
            {   float4* d = reinterpret_cast<float4*>(gY);
                const float4* s4 = reinterpret_cast<const float4*>(g_WpT);
                #pragma unroll
                for (int q = 0; q < 4; q++) d[gt + q*256] = s4[1024 + gt + q*256];
            }
            GBAR();
            #pragma unroll 4
            for (int c = 0; c < 32; c++) {
                const unsigned long long wd = dup2(gY[c*128 + o]);
                const ulonglong2 p0 = *reinterpret_cast<const ulonglong2*>(gPB + (c+32)*16 + rh*8);
                const ulonglong2 p1 = *reinterpret_cast<const ulonglong2*>(gPB + (c+32)*16 + rh*8 + 4);
                fma2(a01, p0.x, wd); fma2(a23, p0.y, wd);
                fma2(a45, p1.x, wd); fma2(a67, p1.y, wd);
            }
            float av[8];
            unpk(a01, av[0], av[1]); unpk(a23, av[2], av[3]);
            unpk(a45, av[4], av[5]); unpk(a67, av[6], av[7]);
            #pragma unroll
            for (int k = 0; k < 8; k++) {
                const int br = rh*8 + k, tb = br >> 2, r = br & 3;
                if (tb < nbuf)
                    out[(size_t)((tb0 + tb*tstep)*4 + r) * 128 + o] = fmaxf(av[k], 0.f);
            }
            nbuf = 0;
            tb0 = t + tstep;
        }
    }
}

// ---------------------------------------------------------------------------
extern "C" void kernel_launch(void* const* d_in, const int* in_sizes, int n_in,
                              void* d_out, int out_size)
{
    const float* x       = (const float*)d_in[0];
    const float* W_phys  = (const float*)d_in[1];
    const float* b_phys  = (const float*)d_in[2];
    const float* W_obj   = (const float*)d_in[3];
    const float* b_obj   = (const float*)d_in[4];
    const float* W_mine  = (const float*)d_in[5];
    const float* b_mine  = (const float*)d_in[6];
    const float* W_prog  = (const float*)d_in[7];
    const float* b_prog  = (const float*)d_in[8];
    const float* W_seq   = (const float*)d_in[9];
    const float* b_seq   = (const float*)d_in[10];
    const float* P_phys  = (const float*)d_in[11];
    const float* pb_phys = (const float*)d_in[12];
    const float* P_obj   = (const float*)d_in[13];
    const float* pb_obj  = (const float*)d_in[14];
    const float* P_mine  = (const float*)d_in[15];
    const float* pb_mine = (const float*)d_in[16];
    const float* P_prog  = (const float*)d_in[17];
    const float* pb_prog = (const float*)d_in[18];
    const float* P_seq   = (const float*)d_in[19];
    const float* pb_seq  = (const float*)d_in[20];
    const float* Wqkv    = (const float*)d_in[21];
    const float* bqkv    = (const float*)d_in[22];
    const float* Wo      = (const float*)d_in[23];
    const float* bo      = (const float*)d_in[24];
    const float* gamma   = (const float*)d_in[25];
    const float* beta    = (const float*)d_in[26];
    const float* Wp      = (const float*)d_in[27];
    const float* bp      = (const float*)d_in[28];
    float* out = (float*)d_out;

    cudaFuncSetAttribute(fused_kernel,
                         cudaFuncAttributeMaxDynamicSharedMemorySize, SMEM_BYTES);

    int dev = 0, sms = 148;
    cudaGetDevice(&dev);
    cudaDeviceGetAttribute(&sms, cudaDevAttrMultiProcessorCount, dev);

    prep_kernel<<<207, 256>>>(Wqkv, bqkv,
                              P_phys, pb_phys, P_obj, pb_obj, P_mine, pb_mine,
                              P_prog, pb_prog, P_seq, pb_seq,
                              W_phys, W_obj, W_mine, W_prog, W_seq,
                              Wo, Wp);

    fused_kernel<<<sms, NTHR, SMEM_BYTES>>>(
        x, b_phys, b_obj, b_mine, b_prog, b_seq,
        bo, gamma, beta, bp, out);
}